// round 1
// baseline (speedup 1.0000x reference)
#include <cuda_runtime.h>
#include <cstdint>

#define B_   2
#define S_   2048
#define E_   2048
#define H_   16
#define KV_  4
#define D_   128
#define WIN_ 1024

// ---------------- scratch (no allocations allowed) ----------------
__device__ float g_q [(size_t)B_ * S_ * H_  * D_];   // [B,S,H,D]
__device__ float g_k [(size_t)B_ * S_ * KV_ * D_];   // [B,S,KV,D]
__device__ float g_v [(size_t)B_ * S_ * KV_ * D_];   // [B,S,KV,D]
__device__ float g_ao[(size_t)B_ * S_ * H_  * D_];   // attention output [B,S,H,D]

// ---------------- GEMM: C[M,N] = A[M,K] * B[N,K]^T (both K-major) ----------------
// 128x128 tile, K-step 8, 256 threads, 8x8 per-thread (4x4 quadrants).
// M, N, K all multiples of 128/8 here, so no bounds checks.
__global__ void __launch_bounds__(256, 2)
gemm_nt(const float* __restrict__ A, const float* __restrict__ Bw,
        float* __restrict__ C, int N, int K)
{
    __shared__ float As[8][128];
    __shared__ float Bs[8][128];

    const int tid = threadIdx.x;
    const int tx  = tid & 15;     // 0..15 -> N quadrant cols
    const int ty  = tid >> 4;     // 0..15 -> M quadrant rows
    const size_t by = (size_t)blockIdx.y * 128;   // M offset
    const size_t bx = (size_t)blockIdx.x * 128;   // N offset

    const int lrow = tid >> 1;          // 0..127
    const int lk   = (tid & 1) * 4;     // 0 or 4
    const float* Ag = A  + (by + lrow) * (size_t)K + lk;
    const float* Bg = Bw + (bx + lrow) * (size_t)K + lk;

    float acc[8][8];
#pragma unroll
    for (int i = 0; i < 8; ++i)
#pragma unroll
        for (int j = 0; j < 8; ++j) acc[i][j] = 0.f;

    for (int k0 = 0; k0 < K; k0 += 8) {
        float4 a4 = *(const float4*)(Ag + k0);
        float4 b4 = *(const float4*)(Bg + k0);
        __syncthreads();
        As[lk + 0][lrow] = a4.x; As[lk + 1][lrow] = a4.y;
        As[lk + 2][lrow] = a4.z; As[lk + 3][lrow] = a4.w;
        Bs[lk + 0][lrow] = b4.x; Bs[lk + 1][lrow] = b4.y;
        Bs[lk + 2][lrow] = b4.z; Bs[lk + 3][lrow] = b4.w;
        __syncthreads();
#pragma unroll
        for (int kk = 0; kk < 8; ++kk) {
            float4 a0 = *(const float4*)&As[kk][ty * 4];
            float4 a1 = *(const float4*)&As[kk][ty * 4 + 64];
            float4 b0 = *(const float4*)&Bs[kk][tx * 4];
            float4 b1 = *(const float4*)&Bs[kk][tx * 4 + 64];
            float ar[8] = {a0.x, a0.y, a0.z, a0.w, a1.x, a1.y, a1.z, a1.w};
            float br[8] = {b0.x, b0.y, b0.z, b0.w, b1.x, b1.y, b1.z, b1.w};
#pragma unroll
            for (int i = 0; i < 8; ++i)
#pragma unroll
                for (int j = 0; j < 8; ++j) acc[i][j] += ar[i] * br[j];
        }
    }

#pragma unroll
    for (int i = 0; i < 8; ++i) {
        int row = (i < 4) ? (int)(by + ty * 4 + i) : (int)(by + 64 + ty * 4 + (i - 4));
        float4 o0 = make_float4(acc[i][0], acc[i][1], acc[i][2], acc[i][3]);
        float4 o1 = make_float4(acc[i][4], acc[i][5], acc[i][6], acc[i][7]);
        *(float4*)(C + (size_t)row * N + bx + tx * 4)      = o0;
        *(float4*)(C + (size_t)row * N + bx + tx * 4 + 64) = o1;
    }
}

// ---------------- RoPE (half-split) + RMS-norm over D=128 ----------------
// buf laid out as rows of D floats, row index = (b*S + s)*nh + h.
__global__ void rope_rms(float* __restrict__ buf,
                         const float* __restrict__ cosb,
                         const float* __restrict__ sinb, int nh)
{
    const int row = blockIdx.x;
    const int s   = (row / nh) % S_;
    float* p = buf + (size_t)row * D_;
    const int t  = threadIdx.x;        // 0..127
    const int dh = t & 63;

    float c  = cosb[s * 64 + dh];
    float sn = sinb[s * 64 + dh];
    float x1 = p[dh];
    float x2 = p[dh + 64];
    float val = (t < 64) ? (x1 * c + x2 * sn) : (x2 * c - x1 * sn);

    float sq = val * val;
#pragma unroll
    for (int o = 16; o; o >>= 1) sq += __shfl_xor_sync(0xffffffffu, sq, o);
    __shared__ float red[4];
    if ((t & 31) == 0) red[t >> 5] = sq;
    __syncthreads();
    float total = red[0] + red[1] + red[2] + red[3];
    p[t] = val * rsqrtf(total * (1.0f / 128.0f) + 1.1920929e-7f);
}

// ---------------- windowed-causal flash attention ----------------
// grid: (S/64, H, B), 256 threads = 8 warps. Warp w owns query rows w*8..w*8+7.
// Score phase: lane owns keys {lane, lane+32}. Output phase: lane owns cols lane*4..+3.
#define ATTN_SMEM_FLOATS (64*128 + 64*129 + 64*128 + 64*64)
__global__ void __launch_bounds__(256, 2)
attn_kernel(const float* __restrict__ qb, const float* __restrict__ kb,
            const float* __restrict__ vb, float* __restrict__ ob)
{
    extern __shared__ float sm[];
    float* Qs = sm;                  // [64][128]
    float* Ks = Qs + 64 * 128;       // [64][129]  (pad -> conflict-free column reads)
    float* Vs = Ks + 64 * 129;       // [64][128]
    float* Ps = Vs + 64 * 128;       // [64][64]   (per-warp row groups)

    const int mblk = blockIdx.x, h = blockIdx.y, b = blockIdx.z;
    const int q0 = mblk * 64;
    const int hk = h >> 2;           // GQA: jnp.repeat -> kv head = h / 4
    const int tid = threadIdx.x, lane = tid & 31, w = tid >> 5;

    // load Q tile
    for (int idx = tid; idx < 64 * 32; idx += 256) {
        int r = idx >> 5, c4 = (idx & 31) * 4;
        *(float4*)&Qs[r * 128 + c4] =
            *(const float4*)(qb + ((size_t)(b * S_ + q0 + r) * H_ + h) * D_ + c4);
    }

    float acc[8][4];
    float mrow[8], lrow[8];
#pragma unroll
    for (int rr = 0; rr < 8; ++rr) {
        mrow[rr] = -1e30f; lrow[rr] = 0.f;
#pragma unroll
        for (int c = 0; c < 4; ++c) acc[rr][c] = 0.f;
    }

    const float scale = 0.08838834764831845f;   // 1/sqrt(128)
    const int t0 = (mblk >= 16) ? (mblk - 16) : 0;

    for (int t = t0; t <= mblk; ++t) {
        const int j0 = t * 64;
        __syncthreads();   // previous tile's smem fully consumed
        // K tile (scalar stores into padded stride 129)
        for (int idx = tid; idx < 64 * 128; idx += 256) {
            int r = idx >> 7, d = idx & 127;
            Ks[r * 129 + d] = kb[((size_t)(b * S_ + j0 + r) * KV_ + hk) * D_ + d];
        }
        // V tile
        for (int idx = tid; idx < 64 * 32; idx += 256) {
            int r = idx >> 5, c4 = (idx & 31) * 4;
            *(float4*)&Vs[r * 128 + c4] =
                *(const float4*)(vb + ((size_t)(b * S_ + j0 + r) * KV_ + hk) * D_ + c4);
        }
        __syncthreads();

        // ---- scores: s[rr][2 keys per lane] ----
        float s0[8], s1[8];
#pragma unroll
        for (int rr = 0; rr < 8; ++rr) { s0[rr] = 0.f; s1[rr] = 0.f; }
#pragma unroll 4
        for (int d = 0; d < 128; ++d) {
            float k0v = Ks[lane * 129 + d];
            float k1v = Ks[(lane + 32) * 129 + d];
#pragma unroll
            for (int rr = 0; rr < 8; ++rr) {
                float qv = Qs[(w * 8 + rr) * 128 + d];
                s0[rr] += qv * k0v;
                s1[rr] += qv * k1v;
            }
        }

        // ---- online softmax update ----
#pragma unroll
        for (int rr = 0; rr < 8; ++rr) {
            int i  = q0 + w * 8 + rr;
            int ja = j0 + lane, jb = j0 + lane + 32;
            bool va  = (ja <= i) && (i - ja < WIN_);
            bool vb_ = (jb <= i) && (i - jb < WIN_);
            float sa = va  ? s0[rr] * scale : -1e30f;
            float sb = vb_ ? s1[rr] * scale : -1e30f;
            float tm = fmaxf(sa, sb);
#pragma unroll
            for (int o = 16; o; o >>= 1) tm = fmaxf(tm, __shfl_xor_sync(0xffffffffu, tm, o));
            float mn = fmaxf(mrow[rr], tm);
            float pa = va  ? __expf(sa - mn) : 0.f;
            float pb = vb_ ? __expf(sb - mn) : 0.f;
            float rs = pa + pb;
#pragma unroll
            for (int o = 16; o; o >>= 1) rs += __shfl_xor_sync(0xffffffffu, rs, o);
            float alpha = __expf(mrow[rr] - mn);
            lrow[rr] = lrow[rr] * alpha + rs;
            mrow[rr] = mn;
#pragma unroll
            for (int c = 0; c < 4; ++c) acc[rr][c] *= alpha;
            Ps[(w * 8 + rr) * 64 + lane]      = pa;
            Ps[(w * 8 + rr) * 64 + lane + 32] = pb;
        }
        __syncwarp();

        // ---- O += P * V ----
#pragma unroll 4
        for (int j = 0; j < 64; ++j) {
            float4 v4 = *(const float4*)&Vs[j * 128 + lane * 4];
#pragma unroll
            for (int rr = 0; rr < 8; ++rr) {
                float p = Ps[(w * 8 + rr) * 64 + j];
                acc[rr][0] += p * v4.x;
                acc[rr][1] += p * v4.y;
                acc[rr][2] += p * v4.z;
                acc[rr][3] += p * v4.w;
            }
        }
    }

#pragma unroll
    for (int rr = 0; rr < 8; ++rr) {
        int i = q0 + w * 8 + rr;
        float inv = 1.0f / lrow[rr];
        float4 o4 = make_float4(acc[rr][0] * inv, acc[rr][1] * inv,
                                acc[rr][2] * inv, acc[rr][3] * inv);
        *(float4*)(ob + ((size_t)(b * S_ + i) * H_ + h) * D_ + lane * 4) = o4;
    }
}

// ---------------- launch ----------------
extern "C" void kernel_launch(void* const* d_in, const int* in_sizes, int n_in,
                              void* d_out, int out_size)
{
    (void)in_sizes; (void)n_in; (void)out_size;
    const float* x    = (const float*)d_in[0];
    const float* cosb = (const float*)d_in[1];
    const float* sinb = (const float*)d_in[2];
    const float* Wq   = (const float*)d_in[3];
    const float* Wk   = (const float*)d_in[4];
    const float* Wv   = (const float*)d_in[5];
    const float* Wo   = (const float*)d_in[6];
    float* out = (float*)d_out;

    float *q, *k, *v, *ao;
    cudaGetSymbolAddress((void**)&q,  g_q);
    cudaGetSymbolAddress((void**)&k,  g_k);
    cudaGetSymbolAddress((void**)&v,  g_v);
    cudaGetSymbolAddress((void**)&ao, g_ao);

    const int M = B_ * S_;   // 4096

    // projections
    gemm_nt<<<dim3((H_  * D_) / 128, M / 128), 256>>>(x, Wq, q, H_  * D_, E_);
    gemm_nt<<<dim3((KV_ * D_) / 128, M / 128), 256>>>(x, Wk, k, KV_ * D_, E_);
    gemm_nt<<<dim3((KV_ * D_) / 128, M / 128), 256>>>(x, Wv, v, KV_ * D_, E_);

    // rope + rmsnorm
    rope_rms<<<M * H_,  128>>>(q, cosb, sinb, H_);
    rope_rms<<<M * KV_, 128>>>(k, cosb, sinb, KV_);

    // attention
    const int smem_bytes = ATTN_SMEM_FLOATS * (int)sizeof(float);  // 114944
    cudaFuncSetAttribute(attn_kernel, cudaFuncAttributeMaxDynamicSharedMemorySize, smem_bytes);
    attn_kernel<<<dim3(S_ / 64, H_, B_), 256, smem_bytes>>>(q, k, v, ao);

    // output projection
    gemm_nt<<<dim3(E_ / 128, M / 128), 256>>>(ao, Wo, out, E_, E_);
}

// round 3
// speedup vs baseline: 1.6896x; 1.6896x over previous
#include <cuda_runtime.h>
#include <cuda_bf16.h>
#include <cstdint>

#define B_   2
#define S_   2048
#define E_   2048
#define H_   16
#define KV_  4
#define D_   128
#define WIN_ 1024

#define MSZ_ (B_ * S_)     // 4096
#define NQ_  (H_ * D_)     // 2048
#define NKV_ (KV_ * D_)    // 512

// ---------------- scratch (no allocations allowed) ----------------
__device__ float g_q [(size_t)MSZ_ * NQ_];
__device__ float g_k [(size_t)MSZ_ * NKV_];
__device__ float g_v [(size_t)MSZ_ * NKV_];
__device__ float g_ao[(size_t)MSZ_ * NQ_];

__device__ __nv_bfloat16 g_xh [(size_t)MSZ_ * E_],  g_xl [(size_t)MSZ_ * E_];
__device__ __nv_bfloat16 g_wqh[(size_t)NQ_  * E_],  g_wql[(size_t)NQ_  * E_];
__device__ __nv_bfloat16 g_wkh[(size_t)NKV_ * E_],  g_wkl[(size_t)NKV_ * E_];
__device__ __nv_bfloat16 g_wvh[(size_t)NKV_ * E_],  g_wvl[(size_t)NKV_ * E_];
__device__ __nv_bfloat16 g_woh[(size_t)E_ * NQ_],   g_wol[(size_t)E_ * NQ_];
__device__ __nv_bfloat16 g_aoh[(size_t)MSZ_ * NQ_], g_aol[(size_t)MSZ_ * NQ_];

// ---------------- helpers ----------------
__device__ __forceinline__ uint32_t smem_u32(const void* p) {
    uint32_t a;
    asm("{ .reg .u64 t; cvta.to.shared.u64 t, %1; cvt.u32.u64 %0, t; }" : "=r"(a) : "l"(p));
    return a;
}
__device__ __forceinline__ void cpasync16(uint32_t dst, const void* src) {
    asm volatile("cp.async.cg.shared.global [%0], [%1], 16;" :: "r"(dst), "l"(src));
}
#define CP_COMMIT()  asm volatile("cp.async.commit_group;" ::: "memory")
#define CP_WAIT(n)   asm volatile("cp.async.wait_group %0;" :: "n"(n) : "memory")

__device__ __forceinline__ void ldsm4(uint32_t* r, uint32_t addr) {
    asm volatile("ldmatrix.sync.aligned.m8n8.x4.shared.b16 {%0,%1,%2,%3}, [%4];"
                 : "=r"(r[0]), "=r"(r[1]), "=r"(r[2]), "=r"(r[3]) : "r"(addr));
}
__device__ __forceinline__ void ldsm2(uint32_t* r, uint32_t addr) {
    asm volatile("ldmatrix.sync.aligned.m8n8.x2.shared.b16 {%0,%1}, [%2];"
                 : "=r"(r[0]), "=r"(r[1]) : "r"(addr));
}
__device__ __forceinline__ void mma16816(float* d, const uint32_t* a, const uint32_t* b) {
    asm volatile("mma.sync.aligned.m16n8k16.row.col.f32.bf16.bf16.f32 "
                 "{%0,%1,%2,%3}, {%4,%5,%6,%7}, {%8,%9}, {%0,%1,%2,%3};"
                 : "+f"(d[0]), "+f"(d[1]), "+f"(d[2]), "+f"(d[3])
                 : "r"(a[0]), "r"(a[1]), "r"(a[2]), "r"(a[3]), "r"(b[0]), "r"(b[1]));
}

// ---------------- bf16 hi/lo split ----------------
__global__ void split_bf16(const float* __restrict__ x,
                           __nv_bfloat16* __restrict__ hi,
                           __nv_bfloat16* __restrict__ lo, int n4)
{
    int i = blockIdx.x * blockDim.x + threadIdx.x;
    if (i >= n4) return;
    float4 v = ((const float4*)x)[i];
    __nv_bfloat16 h0 = __float2bfloat16(v.x), h1 = __float2bfloat16(v.y);
    __nv_bfloat16 h2 = __float2bfloat16(v.z), h3 = __float2bfloat16(v.w);
    __nv_bfloat162 hh0 = {h0, h1}, hh1 = {h2, h3};
    ((__nv_bfloat162*)hi)[i * 2]     = hh0;
    ((__nv_bfloat162*)hi)[i * 2 + 1] = hh1;
    __nv_bfloat162 ll0 = {__float2bfloat16(v.x - __bfloat162float(h0)),
                          __float2bfloat16(v.y - __bfloat162float(h1))};
    __nv_bfloat162 ll1 = {__float2bfloat16(v.z - __bfloat162float(h2)),
                          __float2bfloat16(v.w - __bfloat162float(h3))};
    ((__nv_bfloat162*)lo)[i * 2]     = ll0;
    ((__nv_bfloat162*)lo)[i * 2 + 1] = ll1;
}

// ---------------- HMMA split-bf16 GEMM: C[M,N] = A[M,K] @ B[N,K]^T ----------------
// 128x128 CTA tile, 8 warps (2x4), warp tile 64x32 (4x4 m16n8k16), K-step 32.
// Smem rows padded to 40 halves (80B): ldmatrix 8-row phases hit distinct 16B groups.
#define GSTRIDE 40
#define GTILE_B (128 * GSTRIDE * 2)          // bytes per tile (10240)
#define GEMM_SMEM (8 * GTILE_B)              // 2 stages x 4 tiles = 81920

__global__ void __launch_bounds__(256)
gemm_mma(const __nv_bfloat16* __restrict__ Ah, const __nv_bfloat16* __restrict__ Al,
         const __nv_bfloat16* __restrict__ Bh, const __nv_bfloat16* __restrict__ Bl,
         float* __restrict__ C, int N, int K)
{
    extern __shared__ char smem[];
    const uint32_t sb = smem_u32(smem);

    const int tid  = threadIdx.x;
    const int lane = tid & 31, warp = tid >> 5;
    const int wm   = warp >> 2;          // 0..1 (M)
    const int wn   = warp & 3;           // 0..3 (N)
    const size_t by = (size_t)blockIdx.y * 128;
    const size_t bx = (size_t)blockIdx.x * 128;

    const __nv_bfloat16* srcs[4] = { Ah + by * K, Al + by * K, Bh + bx * K, Bl + bx * K };

    // per-thread load assignment: 2 chunks per tile (512 chunks / 256 threads)
    const int r0 = tid >> 2,           c0 = (tid & 3);
    const int r1 = (tid + 256) >> 2,   c1 = ((tid + 256) & 3);

    auto issue = [&](int kt, int s) {
        const uint32_t base = sb + (uint32_t)s * 4 * GTILE_B;
#pragma unroll
        for (int t = 0; t < 4; ++t) {
            cpasync16(base + t * GTILE_B + (r0 * GSTRIDE + c0 * 8) * 2,
                      srcs[t] + (size_t)r0 * K + kt * 32 + c0 * 8);
            cpasync16(base + t * GTILE_B + (r1 * GSTRIDE + c1 * 8) * 2,
                      srcs[t] + (size_t)r1 * K + kt * 32 + c1 * 8);
        }
    };

    float acc[4][4][4];
#pragma unroll
    for (int mt = 0; mt < 4; ++mt)
#pragma unroll
        for (int nt = 0; nt < 4; ++nt)
#pragma unroll
            for (int e = 0; e < 4; ++e) acc[mt][nt][e] = 0.f;

    const int l2 = lane & 15;
    const int arow = wm * 64 + (lane & 15);      // + mt*16
    const int acol0 = (lane >> 4) * 8;           // + kk
    const int brow = wn * 32 + (l2 & 7);         // + nt*8
    const int bcol0 = (l2 >> 3) * 8;             // + kk

    const int KT = K / 32;
    issue(0, 0);
    CP_COMMIT();

    for (int kt = 0; kt < KT; ++kt) {
        const int s = kt & 1;
        if (kt + 1 < KT) { issue(kt + 1, s ^ 1); CP_COMMIT(); CP_WAIT(1); }
        else             { CP_WAIT(0); }
        __syncthreads();

        const uint32_t base = sb + (uint32_t)s * 4 * GTILE_B;
#pragma unroll
        for (int kk = 0; kk < 32; kk += 16) {
            uint32_t ah[4][4], al[4][4], bh[4][2], bl[4][2];
#pragma unroll
            for (int mt = 0; mt < 4; ++mt) {
                uint32_t off = ((arow + mt * 16) * GSTRIDE + kk + acol0) * 2;
                ldsm4(ah[mt], base + 0 * GTILE_B + off);
                ldsm4(al[mt], base + 1 * GTILE_B + off);
            }
#pragma unroll
            for (int nt = 0; nt < 4; ++nt) {
                uint32_t off = ((brow + nt * 8) * GSTRIDE + kk + bcol0) * 2;
                ldsm2(bh[nt], base + 2 * GTILE_B + off);
                ldsm2(bl[nt], base + 3 * GTILE_B + off);
            }
#pragma unroll
            for (int mt = 0; mt < 4; ++mt)
#pragma unroll
                for (int nt = 0; nt < 4; ++nt) {
                    mma16816(acc[mt][nt], ah[mt], bh[nt]);
                    mma16816(acc[mt][nt], ah[mt], bl[nt]);
                    mma16816(acc[mt][nt], al[mt], bh[nt]);
                }
        }
        __syncthreads();
    }

    // epilogue
#pragma unroll
    for (int mt = 0; mt < 4; ++mt) {
        const int row = (int)by + wm * 64 + mt * 16 + (lane >> 2);
#pragma unroll
        for (int nt = 0; nt < 4; ++nt) {
            const int col = (int)bx + wn * 32 + nt * 8 + (lane & 3) * 2;
            *(float2*)(C + (size_t)row * N + col)       = make_float2(acc[mt][nt][0], acc[mt][nt][1]);
            *(float2*)(C + (size_t)(row + 8) * N + col) = make_float2(acc[mt][nt][2], acc[mt][nt][3]);
        }
    }
}

// ---------------- RoPE (half-split) + RMS-norm over D=128 ----------------
__global__ void rope_rms(float* __restrict__ buf,
                         const float* __restrict__ cosb,
                         const float* __restrict__ sinb, int nh)
{
    const int row = blockIdx.x;
    const int s   = (row / nh) % S_;
    float* p = buf + (size_t)row * D_;
    const int t  = threadIdx.x;
    const int dh = t & 63;

    float c  = cosb[s * 64 + dh];
    float sn = sinb[s * 64 + dh];
    float x1 = p[dh];
    float x2 = p[dh + 64];
    float val = (t < 64) ? (x1 * c + x2 * sn) : (x2 * c - x1 * sn);

    float sq = val * val;
#pragma unroll
    for (int o = 16; o; o >>= 1) sq += __shfl_xor_sync(0xffffffffu, sq, o);
    __shared__ float red[4];
    if ((t & 31) == 0) red[t >> 5] = sq;
    __syncthreads();
    float total = red[0] + red[1] + red[2] + red[3];
    p[t] = val * rsqrtf(total * (1.0f / 128.0f) + 1.1920929e-7f);
}

// ---------------- windowed-causal flash attention (fp32) ----------------
#define ATTN_SMEM_FLOATS (64*128 + 64*129 + 64*128 + 64*64)
__global__ void __launch_bounds__(256, 2)
attn_kernel(const float* __restrict__ qb, const float* __restrict__ kb,
            const float* __restrict__ vb, float* __restrict__ ob)
{
    extern __shared__ float sm[];
    float* Qs = sm;
    float* Ks = Qs + 64 * 128;
    float* Vs = Ks + 64 * 129;
    float* Ps = Vs + 64 * 128;

    const int mblk = blockIdx.x, h = blockIdx.y, b = blockIdx.z;
    const int q0 = mblk * 64;
    const int hk = h >> 2;
    const int tid = threadIdx.x, lane = tid & 31, w = tid >> 5;

    for (int idx = tid; idx < 64 * 32; idx += 256) {
        int r = idx >> 5, c4 = (idx & 31) * 4;
        *(float4*)&Qs[r * 128 + c4] =
            *(const float4*)(qb + ((size_t)(b * S_ + q0 + r) * H_ + h) * D_ + c4);
    }

    float acc[8][4];
    float mrow[8], lrow[8];
#pragma unroll
    for (int rr = 0; rr < 8; ++rr) {
        mrow[rr] = -1e30f; lrow[rr] = 0.f;
#pragma unroll
        for (int c = 0; c < 4; ++c) acc[rr][c] = 0.f;
    }

    const float scale = 0.08838834764831845f;
    const int t0 = (mblk >= 16) ? (mblk - 16) : 0;

    for (int t = t0; t <= mblk; ++t) {
        const int j0 = t * 64;
        __syncthreads();
        for (int idx = tid; idx < 64 * 128; idx += 256) {
            int r = idx >> 7, d = idx & 127;
            Ks[r * 129 + d] = kb[((size_t)(b * S_ + j0 + r) * KV_ + hk) * D_ + d];
        }
        for (int idx = tid; idx < 64 * 32; idx += 256) {
            int r = idx >> 5, c4 = (idx & 31) * 4;
            *(float4*)&Vs[r * 128 + c4] =
                *(const float4*)(vb + ((size_t)(b * S_ + j0 + r) * KV_ + hk) * D_ + c4);
        }
        __syncthreads();

        float s0[8], s1[8];
#pragma unroll
        for (int rr = 0; rr < 8; ++rr) { s0[rr] = 0.f; s1[rr] = 0.f; }
#pragma unroll 4
        for (int d = 0; d < 128; ++d) {
            float k0v = Ks[lane * 129 + d];
            float k1v = Ks[(lane + 32) * 129 + d];
#pragma unroll
            for (int rr = 0; rr < 8; ++rr) {
                float qv = Qs[(w * 8 + rr) * 128 + d];
                s0[rr] += qv * k0v;
                s1[rr] += qv * k1v;
            }
        }

#pragma unroll
        for (int rr = 0; rr < 8; ++rr) {
            int i  = q0 + w * 8 + rr;
            int ja = j0 + lane, jb = j0 + lane + 32;
            bool va  = (ja <= i) && (i - ja < WIN_);
            bool vb_ = (jb <= i) && (i - jb < WIN_);
            float sa = va  ? s0[rr] * scale : -1e30f;
            float sb = vb_ ? s1[rr] * scale : -1e30f;
            float tm = fmaxf(sa, sb);
#pragma unroll
            for (int o = 16; o; o >>= 1) tm = fmaxf(tm, __shfl_xor_sync(0xffffffffu, tm, o));
            float mn = fmaxf(mrow[rr], tm);
            float pa = va  ? __expf(sa - mn) : 0.f;
            float pb = vb_ ? __expf(sb - mn) : 0.f;
            float rs = pa + pb;
#pragma unroll
            for (int o = 16; o; o >>= 1) rs += __shfl_xor_sync(0xffffffffu, rs, o);
            float alpha = __expf(mrow[rr] - mn);
            lrow[rr] = lrow[rr] * alpha + rs;
            mrow[rr] = mn;
#pragma unroll
            for (int c = 0; c < 4; ++c) acc[rr][c] *= alpha;
            Ps[(w * 8 + rr) * 64 + lane]      = pa;
            Ps[(w * 8 + rr) * 64 + lane + 32] = pb;
        }
        __syncwarp();

#pragma unroll 4
        for (int j = 0; j < 64; ++j) {
            float4 v4 = *(const float4*)&Vs[j * 128 + lane * 4];
#pragma unroll
            for (int rr = 0; rr < 8; ++rr) {
                float p = Ps[(w * 8 + rr) * 64 + j];
                acc[rr][0] += p * v4.x;
                acc[rr][1] += p * v4.y;
                acc[rr][2] += p * v4.z;
                acc[rr][3] += p * v4.w;
            }
        }
    }

#pragma unroll
    for (int rr = 0; rr < 8; ++rr) {
        int i = q0 + w * 8 + rr;
        float inv = 1.0f / lrow[rr];
        float4 o4 = make_float4(acc[rr][0] * inv, acc[rr][1] * inv,
                                acc[rr][2] * inv, acc[rr][3] * inv);
        *(float4*)(ob + ((size_t)(b * S_ + i) * H_ + h) * D_ + lane * 4) = o4;
    }
}

// ---------------- launch ----------------
extern "C" void kernel_launch(void* const* d_in, const int* in_sizes, int n_in,
                              void* d_out, int out_size)
{
    (void)in_sizes; (void)n_in; (void)out_size;
    const float* x    = (const float*)d_in[0];
    const float* cosb = (const float*)d_in[1];
    const float* sinb = (const float*)d_in[2];
    const float* Wq   = (const float*)d_in[3];
    const float* Wk   = (const float*)d_in[4];
    const float* Wv   = (const float*)d_in[5];
    const float* Wo   = (const float*)d_in[6];
    float* out = (float*)d_out;

    float *q, *k, *v, *ao;
    cudaGetSymbolAddress((void**)&q,  g_q);
    cudaGetSymbolAddress((void**)&k,  g_k);
    cudaGetSymbolAddress((void**)&v,  g_v);
    cudaGetSymbolAddress((void**)&ao, g_ao);
    __nv_bfloat16 *xh, *xl, *wqh, *wql, *wkh, *wkl, *wvh, *wvl, *woh, *wol, *aoh, *aol;
    cudaGetSymbolAddress((void**)&xh,  g_xh);  cudaGetSymbolAddress((void**)&xl,  g_xl);
    cudaGetSymbolAddress((void**)&wqh, g_wqh); cudaGetSymbolAddress((void**)&wql, g_wql);
    cudaGetSymbolAddress((void**)&wkh, g_wkh); cudaGetSymbolAddress((void**)&wkl, g_wkl);
    cudaGetSymbolAddress((void**)&wvh, g_wvh); cudaGetSymbolAddress((void**)&wvl, g_wvl);
    cudaGetSymbolAddress((void**)&woh, g_woh); cudaGetSymbolAddress((void**)&wol, g_wol);
    cudaGetSymbolAddress((void**)&aoh, g_aoh); cudaGetSymbolAddress((void**)&aol, g_aol);

    const int M = MSZ_;   // 4096
    cudaFuncSetAttribute(gemm_mma, cudaFuncAttributeMaxDynamicSharedMemorySize, GEMM_SMEM);

    auto SPLIT = [](const float* src, __nv_bfloat16* h, __nv_bfloat16* l, size_t n) {
        int n4 = (int)(n / 4);
        split_bf16<<<(n4 + 255) / 256, 256>>>(src, h, l, n4);
    };

    // bf16 hi/lo conversions
    SPLIT(x,  xh,  xl,  (size_t)M * E_);
    SPLIT(Wq, wqh, wql, (size_t)NQ_ * E_);
    SPLIT(Wk, wkh, wkl, (size_t)NKV_ * E_);
    SPLIT(Wv, wvh, wvl, (size_t)NKV_ * E_);
    SPLIT(Wo, woh, wol, (size_t)E_ * NQ_);

    // projections (HMMA)
    gemm_mma<<<dim3(NQ_  / 128, M / 128), 256, GEMM_SMEM>>>(xh, xl, wqh, wql, q, NQ_,  E_);
    gemm_mma<<<dim3(NKV_ / 128, M / 128), 256, GEMM_SMEM>>>(xh, xl, wkh, wkl, k, NKV_, E_);
    gemm_mma<<<dim3(NKV_ / 128, M / 128), 256, GEMM_SMEM>>>(xh, xl, wvh, wvl, v, NKV_, E_);

    // rope + rmsnorm
    rope_rms<<<M * H_,  128>>>(q, cosb, sinb, H_);
    rope_rms<<<M * KV_, 128>>>(k, cosb, sinb, KV_);

    // attention
    const int attn_smem = ATTN_SMEM_FLOATS * (int)sizeof(float);
    cudaFuncSetAttribute(attn_kernel, cudaFuncAttributeMaxDynamicSharedMemorySize, attn_smem);
    attn_kernel<<<dim3(S_ / 64, H_, B_), 256, attn_smem>>>(q, k, v, ao);

    // output projection (HMMA)
    SPLIT(ao, aoh, aol, (size_t)M * NQ_);
    gemm_mma<<<dim3(E_ / 128, M / 128), 256, GEMM_SMEM>>>(aoh, aol, woh, wol, out, E_, NQ_);
}

// round 5
// speedup vs baseline: 1.7309x; 1.0245x over previous
#include <cuda_runtime.h>
#include <cuda_bf16.h>
#include <cstdint>

#define B_   2
#define S_   2048
#define E_   2048
#define H_   16
#define KV_  4
#define D_   128
#define WIN_ 1024

#define MSZ_ (B_ * S_)     // 4096
#define NQ_  (H_ * D_)     // 2048
#define NKV_ (KV_ * D_)    // 512

// ---------------- scratch ----------------
__device__ float g_q [(size_t)MSZ_ * NQ_];
__device__ float g_k [(size_t)MSZ_ * NKV_];
__device__ float g_v [(size_t)MSZ_ * NKV_];

__device__ __nv_bfloat16 g_xh [(size_t)MSZ_ * E_],  g_xl [(size_t)MSZ_ * E_];
__device__ __nv_bfloat16 g_wqh[(size_t)NQ_  * E_],  g_wql[(size_t)NQ_  * E_];
__device__ __nv_bfloat16 g_wkh[(size_t)NKV_ * E_],  g_wkl[(size_t)NKV_ * E_];
__device__ __nv_bfloat16 g_wvh[(size_t)NKV_ * E_],  g_wvl[(size_t)NKV_ * E_];
__device__ __nv_bfloat16 g_woh[(size_t)E_ * NQ_],   g_wol[(size_t)E_ * NQ_];
__device__ __nv_bfloat16 g_aoh[(size_t)MSZ_ * NQ_], g_aol[(size_t)MSZ_ * NQ_];
__device__ __nv_bfloat16 g_qh [(size_t)MSZ_ * NQ_], g_ql [(size_t)MSZ_ * NQ_];
__device__ __nv_bfloat16 g_kh [(size_t)MSZ_ * NKV_], g_kl [(size_t)MSZ_ * NKV_];
__device__ __nv_bfloat16 g_vh [(size_t)MSZ_ * NKV_], g_vl [(size_t)MSZ_ * NKV_];

// ---------------- helpers ----------------
__device__ __forceinline__ uint32_t smem_u32(const void* p) {
    uint32_t a;
    asm("{ .reg .u64 t; cvta.to.shared.u64 t, %1; cvt.u32.u64 %0, t; }" : "=r"(a) : "l"(p));
    return a;
}
__device__ __forceinline__ void cpasync16(uint32_t dst, const void* src) {
    asm volatile("cp.async.cg.shared.global [%0], [%1], 16;" :: "r"(dst), "l"(src));
}
#define CP_COMMIT()  asm volatile("cp.async.commit_group;" ::: "memory")
#define CP_WAIT(n)   asm volatile("cp.async.wait_group %0;" :: "n"(n) : "memory")

__device__ __forceinline__ void ldsm4(uint32_t* r, uint32_t addr) {
    asm volatile("ldmatrix.sync.aligned.m8n8.x4.shared.b16 {%0,%1,%2,%3}, [%4];"
                 : "=r"(r[0]), "=r"(r[1]), "=r"(r[2]), "=r"(r[3]) : "r"(addr));
}
__device__ __forceinline__ void ldsm2(uint32_t* r, uint32_t addr) {
    asm volatile("ldmatrix.sync.aligned.m8n8.x2.shared.b16 {%0,%1}, [%2];"
                 : "=r"(r[0]), "=r"(r[1]) : "r"(addr));
}
__device__ __forceinline__ void ldsm4t(uint32_t* r, uint32_t addr) {
    asm volatile("ldmatrix.sync.aligned.m8n8.x4.trans.shared.b16 {%0,%1,%2,%3}, [%4];"
                 : "=r"(r[0]), "=r"(r[1]), "=r"(r[2]), "=r"(r[3]) : "r"(addr));
}
__device__ __forceinline__ void mma16816(float* d, const uint32_t* a, const uint32_t* b) {
    asm volatile("mma.sync.aligned.m16n8k16.row.col.f32.bf16.bf16.f32 "
                 "{%0,%1,%2,%3}, {%4,%5,%6,%7}, {%8,%9}, {%0,%1,%2,%3};"
                 : "+f"(d[0]), "+f"(d[1]), "+f"(d[2]), "+f"(d[3])
                 : "r"(a[0]), "r"(a[1]), "r"(a[2]), "r"(a[3]), "r"(b[0]), "r"(b[1]));
}
__device__ __forceinline__ void split2(float a, float b, uint32_t& hi, uint32_t& lo) {
    __nv_bfloat16 ha = __float2bfloat16(a), hb = __float2bfloat16(b);
    __nv_bfloat162 h2; h2.x = ha; h2.y = hb;
    hi = *reinterpret_cast<uint32_t*>(&h2);
    __nv_bfloat162 l2;
    l2.x = __float2bfloat16(a - __bfloat162float(ha));
    l2.y = __float2bfloat16(b - __bfloat162float(hb));
    lo = *reinterpret_cast<uint32_t*>(&l2);
}

// ---------------- bf16 hi/lo split ----------------
__global__ void split_bf16(const float* __restrict__ x,
                           __nv_bfloat16* __restrict__ hi,
                           __nv_bfloat16* __restrict__ lo, int n4)
{
    int i = blockIdx.x * blockDim.x + threadIdx.x;
    if (i >= n4) return;
    float4 v = ((const float4*)x)[i];
    uint32_t h0, l0, h1, l1;
    split2(v.x, v.y, h0, l0);
    split2(v.z, v.w, h1, l1);
    ((uint32_t*)hi)[i * 2]     = h0;
    ((uint32_t*)hi)[i * 2 + 1] = h1;
    ((uint32_t*)lo)[i * 2]     = l0;
    ((uint32_t*)lo)[i * 2 + 1] = l1;
}

// ---------------- HMMA split-bf16 GEMM (4-stage cp.async pipeline) ----------------
#define GSTRIDE 40
#define GTILE_B (128 * GSTRIDE * 2)          // 10240
#define GEMM_SMEM (16 * GTILE_B)             // 4 stages x 4 tiles = 163840

__global__ void __launch_bounds__(256)
gemm_mma(const __nv_bfloat16* __restrict__ Ah, const __nv_bfloat16* __restrict__ Al,
         const __nv_bfloat16* __restrict__ Bh, const __nv_bfloat16* __restrict__ Bl,
         float* __restrict__ C, int N, int K)
{
    extern __shared__ char smem[];
    const uint32_t sb = smem_u32(smem);

    const int tid  = threadIdx.x;
    const int lane = tid & 31, warp = tid >> 5;
    const int wm   = warp >> 2;
    const int wn   = warp & 3;
    const size_t by = (size_t)blockIdx.y * 128;
    const size_t bx = (size_t)blockIdx.x * 128;

    const __nv_bfloat16* srcs[4] = { Ah + by * K, Al + by * K, Bh + bx * K, Bl + bx * K };

    const int r0 = tid >> 2,  c0 = (tid & 3);
    const int r1 = r0 + 64;

    auto issue = [&](int kt, int s) {
        const uint32_t base = sb + (uint32_t)s * 4 * GTILE_B;
#pragma unroll
        for (int t = 0; t < 4; ++t) {
            cpasync16(base + t * GTILE_B + (r0 * GSTRIDE + c0 * 8) * 2,
                      srcs[t] + (size_t)r0 * K + kt * 32 + c0 * 8);
            cpasync16(base + t * GTILE_B + (r1 * GSTRIDE + c0 * 8) * 2,
                      srcs[t] + (size_t)r1 * K + kt * 32 + c0 * 8);
        }
    };

    float acc[4][4][4];
#pragma unroll
    for (int mt = 0; mt < 4; ++mt)
#pragma unroll
        for (int nt = 0; nt < 4; ++nt)
#pragma unroll
            for (int e = 0; e < 4; ++e) acc[mt][nt][e] = 0.f;

    const int l2 = lane & 15;
    const int arow = wm * 64 + (lane & 15);
    const int acol0 = (lane >> 4) * 8;
    const int brow = wn * 32 + (l2 & 7);
    const int bcol0 = (l2 >> 3) * 8;

    const int KT = K / 32;
    for (int p = 0; p < 3 && p < KT; ++p) { issue(p, p & 3); CP_COMMIT(); }

    for (int kt = 0; kt < KT; ++kt) {
        if (kt + 2 < KT)      CP_WAIT(2);
        else if (kt + 1 < KT) CP_WAIT(1);
        else                  CP_WAIT(0);
        __syncthreads();
        if (kt + 3 < KT) { issue(kt + 3, (kt + 3) & 3); CP_COMMIT(); }

        const uint32_t base = sb + (uint32_t)(kt & 3) * 4 * GTILE_B;
#pragma unroll
        for (int kk = 0; kk < 32; kk += 16) {
            uint32_t ah[4][4], al[4][4], bh[4][2], bl[4][2];
#pragma unroll
            for (int mt = 0; mt < 4; ++mt) {
                uint32_t off = ((arow + mt * 16) * GSTRIDE + kk + acol0) * 2;
                ldsm4(ah[mt], base + 0 * GTILE_B + off);
                ldsm4(al[mt], base + 1 * GTILE_B + off);
            }
#pragma unroll
            for (int nt = 0; nt < 4; ++nt) {
                uint32_t off = ((brow + nt * 8) * GSTRIDE + kk + bcol0) * 2;
                ldsm2(bh[nt], base + 2 * GTILE_B + off);
                ldsm2(bl[nt], base + 3 * GTILE_B + off);
            }
#pragma unroll
            for (int mt = 0; mt < 4; ++mt)
#pragma unroll
                for (int nt = 0; nt < 4; ++nt) {
                    mma16816(acc[mt][nt], ah[mt], bh[nt]);
                    mma16816(acc[mt][nt], ah[mt], bl[nt]);
                    mma16816(acc[mt][nt], al[mt], bh[nt]);
                }
        }
    }

#pragma unroll
    for (int mt = 0; mt < 4; ++mt) {
        const int row = (int)by + wm * 64 + mt * 16 + (lane >> 2);
#pragma unroll
        for (int nt = 0; nt < 4; ++nt) {
            const int col = (int)bx + wn * 32 + nt * 8 + (lane & 3) * 2;
            *(float2*)(C + (size_t)row * N + col)       = make_float2(acc[mt][nt][0], acc[mt][nt][1]);
            *(float2*)(C + (size_t)(row + 8) * N + col) = make_float2(acc[mt][nt][2], acc[mt][nt][3]);
        }
    }
}

// ---------------- RoPE + RMS-norm -> bf16 hi/lo splits ----------------
__global__ void rope_rms_split(const float* __restrict__ buf,
                               __nv_bfloat16* __restrict__ oh,
                               __nv_bfloat16* __restrict__ ol,
                               const float* __restrict__ cosb,
                               const float* __restrict__ sinb, int nh)
{
    const int row = blockIdx.x;
    const int s   = (row / nh) % S_;
    const float* p = buf + (size_t)row * D_;
    const int t  = threadIdx.x;
    const int dh = t & 63;

    float c  = cosb[s * 64 + dh];
    float sn = sinb[s * 64 + dh];
    float x1 = p[dh];
    float x2 = p[dh + 64];
    float val = (t < 64) ? (x1 * c + x2 * sn) : (x2 * c - x1 * sn);

    float sq = val * val;
#pragma unroll
    for (int o = 16; o; o >>= 1) sq += __shfl_xor_sync(0xffffffffu, sq, o);
    __shared__ float red[4];
    if ((t & 31) == 0) red[t >> 5] = sq;
    __syncthreads();
    float total = red[0] + red[1] + red[2] + red[3];
    float y = val * rsqrtf(total * (1.0f / 128.0f) + 1.1920929e-7f);
    __nv_bfloat16 h = __float2bfloat16(y);
    oh[(size_t)row * D_ + t] = h;
    ol[(size_t)row * D_ + t] = __float2bfloat16(y - __bfloat162float(h));
}

// ---------------- windowed-causal flash attention (split-bf16 HMMA) ----------------
// block: 64 queries x 1 head; 4 warps, warp w owns query rows [w*16, w*16+16).
#define LDH 136
#define ATILE_B (64 * LDH * 2)       // 17408
#define ATTN_SMEM (6 * ATILE_B)      // 104448

__global__ void __launch_bounds__(128, 2)
attn_mma(const __nv_bfloat16* __restrict__ qh, const __nv_bfloat16* __restrict__ ql,
         const __nv_bfloat16* __restrict__ kh, const __nv_bfloat16* __restrict__ kl,
         const __nv_bfloat16* __restrict__ vh, const __nv_bfloat16* __restrict__ vl,
         __nv_bfloat16* __restrict__ aoh, __nv_bfloat16* __restrict__ aol)
{
    extern __shared__ char smem[];
    const uint32_t sb = smem_u32(smem);
    const uint32_t QH = sb,              QL = sb + ATILE_B;
    const uint32_t KH = sb + 2*ATILE_B,  KL = sb + 3*ATILE_B;
    const uint32_t VH = sb + 4*ATILE_B,  VL = sb + 5*ATILE_B;

    const int mblk = blockIdx.x, h = blockIdx.y, b = blockIdx.z;
    const int q0 = mblk * 64;
    const int hk = h >> 2;
    const int tid = threadIdx.x, lane = tid & 31, w = tid >> 5;

    // Q tile load (once)
    for (int i = tid; i < 1024; i += 128) {
        int r = i >> 4, c = (i & 15) * 8;
        size_t g = ((size_t)(b * S_ + q0 + r) * H_ + h) * D_ + c;
        uint32_t o = (uint32_t)(r * LDH + c) * 2;
        cpasync16(QH + o, qh + g);
        cpasync16(QL + o, ql + g);
    }
    CP_COMMIT();

    float o_acc[16][4];
#pragma unroll
    for (int nt = 0; nt < 16; ++nt)
#pragma unroll
        for (int e = 0; e < 4; ++e) o_acc[nt][e] = 0.f;
    float m_lo = -1e30f, m_hi = -1e30f, l_lo = 0.f, l_hi = 0.f;

    const float scale = 0.08838834764831845f;
    const int t0 = (mblk >= 16) ? (mblk - 16) : 0;
    const int lane2 = lane & 15;

    const uint32_t a_off = (uint32_t)((w * 16 + (lane & 15)) * LDH + (lane >> 4) * 8) * 2;
    const int i_lo = q0 + w * 16 + (lane >> 2);
    const int i_hi = i_lo + 8;

    for (int t = t0; t <= mblk; ++t) {
        const int j0 = t * 64;
        __syncthreads();   // prior tile fully consumed
        for (int i = tid; i < 1024; i += 128) {
            int r = i >> 4, c = (i & 15) * 8;
            size_t g = ((size_t)(b * S_ + j0 + r) * KV_ + hk) * D_ + c;
            uint32_t o = (uint32_t)(r * LDH + c) * 2;
            cpasync16(KH + o, kh + g);
            cpasync16(KL + o, kl + g);
            cpasync16(VH + o, vh + g);
            cpasync16(VL + o, vl + g);
        }
        CP_COMMIT();
        CP_WAIT(0);
        __syncthreads();

        // ---- S = Q K^T (split) ----
        float s[8][4];
#pragma unroll
        for (int nt = 0; nt < 8; ++nt)
#pragma unroll
            for (int e = 0; e < 4; ++e) s[nt][e] = 0.f;

#pragma unroll
        for (int kk = 0; kk < 128; kk += 16) {
            uint32_t ah[4], al[4];
            ldsm4(ah, QH + a_off + kk * 2);
            ldsm4(al, QL + a_off + kk * 2);
#pragma unroll
            for (int nt = 0; nt < 8; ++nt) {
                uint32_t off = (uint32_t)((nt * 8 + (lane2 & 7)) * LDH + kk + ((lane2 >> 3) & 1) * 8) * 2;
                uint32_t bh2[2], bl2[2];
                ldsm2(bh2, KH + off);
                ldsm2(bl2, KL + off);
                mma16816(s[nt], ah, bh2);
                mma16816(s[nt], ah, bl2);
                mma16816(s[nt], al, bh2);
            }
        }

        // ---- masked online softmax ----
        float mx_lo = -1e30f, mx_hi = -1e30f;
#pragma unroll
        for (int nt = 0; nt < 8; ++nt) {
            int jb = j0 + nt * 8 + (lane & 3) * 2;
            bool v0 = (jb     <= i_lo) && (i_lo - jb     < WIN_);
            bool v1 = (jb + 1 <= i_lo) && (i_lo - jb - 1 < WIN_);
            bool v2 = (jb     <= i_hi) && (i_hi - jb     < WIN_);
            bool v3 = (jb + 1 <= i_hi) && (i_hi - jb - 1 < WIN_);
            s[nt][0] = v0 ? s[nt][0] * scale : -1e30f;
            s[nt][1] = v1 ? s[nt][1] * scale : -1e30f;
            s[nt][2] = v2 ? s[nt][2] * scale : -1e30f;
            s[nt][3] = v3 ? s[nt][3] * scale : -1e30f;
            mx_lo = fmaxf(mx_lo, fmaxf(s[nt][0], s[nt][1]));
            mx_hi = fmaxf(mx_hi, fmaxf(s[nt][2], s[nt][3]));
        }
        mx_lo = fmaxf(mx_lo, __shfl_xor_sync(0xffffffffu, mx_lo, 1));
        mx_lo = fmaxf(mx_lo, __shfl_xor_sync(0xffffffffu, mx_lo, 2));
        mx_hi = fmaxf(mx_hi, __shfl_xor_sync(0xffffffffu, mx_hi, 1));
        mx_hi = fmaxf(mx_hi, __shfl_xor_sync(0xffffffffu, mx_hi, 2));

        float mn_lo = fmaxf(m_lo, mx_lo), mn_hi = fmaxf(m_hi, mx_hi);
        float al_lo = __expf(m_lo - mn_lo), al_hi = __expf(m_hi - mn_hi);
        float sum_lo = 0.f, sum_hi = 0.f;
#pragma unroll
        for (int nt = 0; nt < 8; ++nt) {
            s[nt][0] = __expf(s[nt][0] - mn_lo);
            s[nt][1] = __expf(s[nt][1] - mn_lo);
            s[nt][2] = __expf(s[nt][2] - mn_hi);
            s[nt][3] = __expf(s[nt][3] - mn_hi);
            sum_lo += s[nt][0] + s[nt][1];
            sum_hi += s[nt][2] + s[nt][3];
        }
        sum_lo += __shfl_xor_sync(0xffffffffu, sum_lo, 1);
        sum_lo += __shfl_xor_sync(0xffffffffu, sum_lo, 2);
        sum_hi += __shfl_xor_sync(0xffffffffu, sum_hi, 1);
        sum_hi += __shfl_xor_sync(0xffffffffu, sum_hi, 2);
        l_lo = l_lo * al_lo + sum_lo;  m_lo = mn_lo;
        l_hi = l_hi * al_hi + sum_hi;  m_hi = mn_hi;
#pragma unroll
        for (int nt = 0; nt < 16; ++nt) {
            o_acc[nt][0] *= al_lo; o_acc[nt][1] *= al_lo;
            o_acc[nt][2] *= al_hi; o_acc[nt][3] *= al_hi;
        }

        // ---- O += P V (split) ----
#pragma unroll
        for (int kc = 0; kc < 4; ++kc) {
            uint32_t aph[4], apl[4];
            split2(s[2*kc][0],   s[2*kc][1],   aph[0], apl[0]);
            split2(s[2*kc][2],   s[2*kc][3],   aph[1], apl[1]);
            split2(s[2*kc+1][0], s[2*kc+1][1], aph[2], apl[2]);
            split2(s[2*kc+1][2], s[2*kc+1][3], aph[3], apl[3]);

            uint32_t vr = (uint32_t)(kc * 16 + (lane & 7) + ((lane >> 3) & 1) * 8) * LDH
                        + (uint32_t)((lane >> 4) * 8);
#pragma unroll
            for (int dt = 0; dt < 8; ++dt) {
                uint32_t off = (vr + dt * 16) * 2;
                uint32_t bvh[4], bvl[4];
                ldsm4t(bvh, VH + off);
                ldsm4t(bvl, VL + off);
                mma16816(o_acc[2*dt],   aph, bvh);
                mma16816(o_acc[2*dt],   aph, bvl);
                mma16816(o_acc[2*dt],   apl, bvh);
                mma16816(o_acc[2*dt+1], aph, bvh + 2);
                mma16816(o_acc[2*dt+1], aph, bvl + 2);
                mma16816(o_acc[2*dt+1], apl, bvh + 2);
            }
        }
    }

    // ---- epilogue: normalize, split to bf16 hi/lo, store ----
    float inv_lo = 1.0f / l_lo, inv_hi = 1.0f / l_hi;
#pragma unroll
    for (int nt = 0; nt < 16; ++nt) {
        int c = nt * 8 + (lane & 3) * 2;
        size_t glo = ((size_t)(b * S_ + i_lo) * H_ + h) * D_ + c;
        size_t ghi = ((size_t)(b * S_ + i_hi) * H_ + h) * D_ + c;
        uint32_t hh, ll;
        split2(o_acc[nt][0] * inv_lo, o_acc[nt][1] * inv_lo, hh, ll);
        *(uint32_t*)(aoh + glo) = hh;
        *(uint32_t*)(aol + glo) = ll;
        split2(o_acc[nt][2] * inv_hi, o_acc[nt][3] * inv_hi, hh, ll);
        *(uint32_t*)(aoh + ghi) = hh;
        *(uint32_t*)(aol + ghi) = ll;
    }
}

// ---------------- launch ----------------
extern "C" void kernel_launch(void* const* d_in, const int* in_sizes, int n_in,
                              void* d_out, int out_size)
{
    (void)in_sizes; (void)n_in; (void)out_size;
    const float* x    = (const float*)d_in[0];
    const float* cosb = (const float*)d_in[1];
    const float* sinb = (const float*)d_in[2];
    const float* Wq   = (const float*)d_in[3];
    const float* Wk   = (const float*)d_in[4];
    const float* Wv   = (const float*)d_in[5];
    const float* Wo   = (const float*)d_in[6];
    float* out = (float*)d_out;

    float *q, *k, *v;
    cudaGetSymbolAddress((void**)&q, g_q);
    cudaGetSymbolAddress((void**)&k, g_k);
    cudaGetSymbolAddress((void**)&v, g_v);
    __nv_bfloat16 *xh, *xl, *wqh, *wql, *wkh, *wkl, *wvh, *wvl, *woh, *wol, *aoh, *aol;
    __nv_bfloat16 *qh, *ql, *kh, *kl, *vh, *vl;
    cudaGetSymbolAddress((void**)&xh,  g_xh);  cudaGetSymbolAddress((void**)&xl,  g_xl);
    cudaGetSymbolAddress((void**)&wqh, g_wqh); cudaGetSymbolAddress((void**)&wql, g_wql);
    cudaGetSymbolAddress((void**)&wkh, g_wkh); cudaGetSymbolAddress((void**)&wkl, g_wkl);
    cudaGetSymbolAddress((void**)&wvh, g_wvh); cudaGetSymbolAddress((void**)&wvl, g_wvl);
    cudaGetSymbolAddress((void**)&woh, g_woh); cudaGetSymbolAddress((void**)&wol, g_wol);
    cudaGetSymbolAddress((void**)&aoh, g_aoh); cudaGetSymbolAddress((void**)&aol, g_aol);
    cudaGetSymbolAddress((void**)&qh,  g_qh);  cudaGetSymbolAddress((void**)&ql,  g_ql);
    cudaGetSymbolAddress((void**)&kh,  g_kh);  cudaGetSymbolAddress((void**)&kl,  g_kl);
    cudaGetSymbolAddress((void**)&vh,  g_vh);  cudaGetSymbolAddress((void**)&vl,  g_vl);

    const int M = MSZ_;   // 4096
    cudaFuncSetAttribute(gemm_mma, cudaFuncAttributeMaxDynamicSharedMemorySize, GEMM_SMEM);
    cudaFuncSetAttribute(attn_mma, cudaFuncAttributeMaxDynamicSharedMemorySize, ATTN_SMEM);

    auto SPLIT = [](const float* src, __nv_bfloat16* h, __nv_bfloat16* l, size_t n) {
        int n4 = (int)(n / 4);
        split_bf16<<<(n4 + 255) / 256, 256>>>(src, h, l, n4);
    };

    SPLIT(x,  xh,  xl,  (size_t)M * E_);
    SPLIT(Wq, wqh, wql, (size_t)NQ_ * E_);
    SPLIT(Wk, wkh, wkl, (size_t)NKV_ * E_);
    SPLIT(Wv, wvh, wvl, (size_t)NKV_ * E_);
    SPLIT(Wo, woh, wol, (size_t)E_ * NQ_);

    gemm_mma<<<dim3(NQ_  / 128, M / 128), 256, GEMM_SMEM>>>(xh, xl, wqh, wql, q, NQ_,  E_);
    gemm_mma<<<dim3(NKV_ / 128, M / 128), 256, GEMM_SMEM>>>(xh, xl, wkh, wkl, k, NKV_, E_);
    gemm_mma<<<dim3(NKV_ / 128, M / 128), 256, GEMM_SMEM>>>(xh, xl, wvh, wvl, v, NKV_, E_);

    SPLIT(v, vh, vl, (size_t)M * NKV_);
    rope_rms_split<<<M * H_,  128>>>(q, qh, ql, cosb, sinb, H_);
    rope_rms_split<<<M * KV_, 128>>>(k, kh, kl, cosb, sinb, KV_);

    attn_mma<<<dim3(S_ / 64, H_, B_), 128, ATTN_SMEM>>>(qh, ql, kh, kl, vh, vl, aoh, aol);

    gemm_mma<<<dim3(E_ / 128, M / 128), 256, GEMM_SMEM>>>(aoh, aol, woh, wol, out, E_, NQ_);
}

// round 8
// speedup vs baseline: 2.6135x; 1.5099x over previous
#include <cuda_runtime.h>
#include <cuda_bf16.h>
#include <cstdint>

#define B_   2
#define S_   2048
#define E_   2048
#define H_   16
#define KV_  4
#define D_   128
#define WIN_ 1024

#define MSZ_ (B_ * S_)     // 4096
#define NQ_  (H_ * D_)     // 2048
#define NKV_ (KV_ * D_)    // 512
#define NQKV_ (NQ_ + 2 * NKV_)   // 3072

// ---------------- scratch ----------------
__device__ float g_qkv[(size_t)MSZ_ * NQKV_];   // packed [M, q|k|v]

__device__ __nv_bfloat16 g_xh [(size_t)MSZ_ * E_],   g_xl [(size_t)MSZ_ * E_];
__device__ __nv_bfloat16 g_wph[(size_t)NQKV_ * E_],  g_wpl[(size_t)NQKV_ * E_];  // packed Wq|Wk|Wv
__device__ __nv_bfloat16 g_woh[(size_t)E_ * NQ_],    g_wol[(size_t)E_ * NQ_];
__device__ __nv_bfloat16 g_aoh[(size_t)MSZ_ * NQ_],  g_aol[(size_t)MSZ_ * NQ_];
__device__ __nv_bfloat16 g_qh [(size_t)MSZ_ * NQ_],  g_ql [(size_t)MSZ_ * NQ_];
__device__ __nv_bfloat16 g_kh [(size_t)MSZ_ * NKV_], g_kl [(size_t)MSZ_ * NKV_];
__device__ __nv_bfloat16 g_vh [(size_t)MSZ_ * NKV_], g_vl [(size_t)MSZ_ * NKV_];

// ---------------- helpers ----------------
__device__ __forceinline__ uint32_t smem_u32(const void* p) {
    uint32_t a;
    asm("{ .reg .u64 t; cvta.to.shared.u64 t, %1; cvt.u32.u64 %0, t; }" : "=r"(a) : "l"(p));
    return a;
}
__device__ __forceinline__ void cpasync16(uint32_t dst, const void* src) {
    asm volatile("cp.async.cg.shared.global [%0], [%1], 16;" :: "r"(dst), "l"(src));
}
#define CP_COMMIT()  asm volatile("cp.async.commit_group;" ::: "memory")
#define CP_WAIT(n)   asm volatile("cp.async.wait_group %0;" :: "n"(n) : "memory")

__device__ __forceinline__ void ldsm4(uint32_t* r, uint32_t addr) {
    asm volatile("ldmatrix.sync.aligned.m8n8.x4.shared.b16 {%0,%1,%2,%3}, [%4];"
                 : "=r"(r[0]), "=r"(r[1]), "=r"(r[2]), "=r"(r[3]) : "r"(addr));
}
__device__ __forceinline__ void ldsm2(uint32_t* r, uint32_t addr) {
    asm volatile("ldmatrix.sync.aligned.m8n8.x2.shared.b16 {%0,%1}, [%2];"
                 : "=r"(r[0]), "=r"(r[1]) : "r"(addr));
}
__device__ __forceinline__ void ldsm4t(uint32_t* r, uint32_t addr) {
    asm volatile("ldmatrix.sync.aligned.m8n8.x4.trans.shared.b16 {%0,%1,%2,%3}, [%4];"
                 : "=r"(r[0]), "=r"(r[1]), "=r"(r[2]), "=r"(r[3]) : "r"(addr));
}
__device__ __forceinline__ void mma16816(float* d, const uint32_t* a, const uint32_t* b) {
    asm volatile("mma.sync.aligned.m16n8k16.row.col.f32.bf16.bf16.f32 "
                 "{%0,%1,%2,%3}, {%4,%5,%6,%7}, {%8,%9}, {%0,%1,%2,%3};"
                 : "+f"(d[0]), "+f"(d[1]), "+f"(d[2]), "+f"(d[3])
                 : "r"(a[0]), "r"(a[1]), "r"(a[2]), "r"(a[3]), "r"(b[0]), "r"(b[1]));
}
__device__ __forceinline__ void split2(float a, float b, uint32_t& hi, uint32_t& lo) {
    __nv_bfloat16 ha = __float2bfloat16(a), hb = __float2bfloat16(b);
    __nv_bfloat162 h2; h2.x = ha; h2.y = hb;
    hi = *reinterpret_cast<uint32_t*>(&h2);
    __nv_bfloat162 l2;
    l2.x = __float2bfloat16(a - __bfloat162float(ha));
    l2.y = __float2bfloat16(b - __bfloat162float(hb));
    lo = *reinterpret_cast<uint32_t*>(&l2);
}

// ---------------- bf16 hi/lo split (contiguous) ----------------
__global__ void split_bf16(const float* __restrict__ x,
                           __nv_bfloat16* __restrict__ hi,
                           __nv_bfloat16* __restrict__ lo, int n4)
{
    int i = blockIdx.x * blockDim.x + threadIdx.x;
    if (i >= n4) return;
    float4 v = ((const float4*)x)[i];
    uint32_t h0, l0, h1, l1;
    split2(v.x, v.y, h0, l0);
    split2(v.z, v.w, h1, l1);
    ((uint32_t*)hi)[i * 2]     = h0;
    ((uint32_t*)hi)[i * 2 + 1] = h1;
    ((uint32_t*)lo)[i * 2]     = l0;
    ((uint32_t*)lo)[i * 2 + 1] = l1;
}

// split V out of the packed QKV buffer (strided read)
// [FIX R8: V lives at column offset NQ_+NKV_, not NQ_ (that's K)]
__global__ void split_v(const float* __restrict__ qkv,
                        __nv_bfloat16* __restrict__ vh, __nv_bfloat16* __restrict__ vl)
{
    int i = blockIdx.x * blockDim.x + threadIdx.x;   // over MSZ_*128 float4 chunks
    if (i >= MSZ_ * 128) return;
    int row = i >> 7, c4 = (i & 127) * 4;
    float4 v = *(const float4*)(qkv + (size_t)row * NQKV_ + (NQ_ + NKV_) + c4);
    uint32_t h0, l0, h1, l1;
    split2(v.x, v.y, h0, l0);
    split2(v.z, v.w, h1, l1);
    size_t o = ((size_t)row * NKV_ + c4) >> 1;
    ((uint32_t*)vh)[o]     = h0;
    ((uint32_t*)vh)[o + 1] = h1;
    ((uint32_t*)vl)[o]     = l0;
    ((uint32_t*)vl)[o + 1] = l1;
}

// ---------------- HMMA split-bf16 GEMM (2-stage cp.async pipeline) ----------------
#define GSTRIDE 40
#define GTILE_B (128 * GSTRIDE * 2)          // 10240
#define GEMM_SMEM (8 * GTILE_B)              // 2 stages x 4 tiles = 81920

__global__ void __launch_bounds__(256)
gemm_mma(const __nv_bfloat16* __restrict__ Ah, const __nv_bfloat16* __restrict__ Al,
         const __nv_bfloat16* __restrict__ Bh, const __nv_bfloat16* __restrict__ Bl,
         float* __restrict__ C, int N, int K)
{
    extern __shared__ char smem[];
    const uint32_t sb = smem_u32(smem);

    const int tid  = threadIdx.x;
    const int lane = tid & 31, warp = tid >> 5;
    const int wm   = warp >> 2;
    const int wn   = warp & 3;
    const size_t by = (size_t)blockIdx.y * 128;
    const size_t bx = (size_t)blockIdx.x * 128;

    const __nv_bfloat16* srcs[4] = { Ah + by * K, Al + by * K, Bh + bx * K, Bl + bx * K };

    const int r0 = tid >> 2,  c0 = (tid & 3);
    const int r1 = r0 + 64;

    auto issue = [&](int kt, int s) {
        const uint32_t base = sb + (uint32_t)s * 4 * GTILE_B;
#pragma unroll
        for (int t = 0; t < 4; ++t) {
            cpasync16(base + t * GTILE_B + (r0 * GSTRIDE + c0 * 8) * 2,
                      srcs[t] + (size_t)r0 * K + kt * 32 + c0 * 8);
            cpasync16(base + t * GTILE_B + (r1 * GSTRIDE + c0 * 8) * 2,
                      srcs[t] + (size_t)r1 * K + kt * 32 + c0 * 8);
        }
    };

    float acc[4][4][4];
#pragma unroll
    for (int mt = 0; mt < 4; ++mt)
#pragma unroll
        for (int nt = 0; nt < 4; ++nt)
#pragma unroll
            for (int e = 0; e < 4; ++e) acc[mt][nt][e] = 0.f;

    const int l2 = lane & 15;
    const int arow = wm * 64 + (lane & 15);
    const int acol0 = (lane >> 4) * 8;
    const int brow = wn * 32 + (l2 & 7);
    const int bcol0 = (l2 >> 3) * 8;

    const int KT = K / 32;
    issue(0, 0);
    CP_COMMIT();

    for (int kt = 0; kt < KT; ++kt) {
        const int s = kt & 1;
        if (kt + 1 < KT) { issue(kt + 1, s ^ 1); CP_COMMIT(); CP_WAIT(1); }
        else             { CP_WAIT(0); }
        __syncthreads();

        const uint32_t base = sb + (uint32_t)s * 4 * GTILE_B;
#pragma unroll
        for (int kk = 0; kk < 32; kk += 16) {
            uint32_t ah[4][4], al[4][4], bh[4][2], bl[4][2];
#pragma unroll
            for (int mt = 0; mt < 4; ++mt) {
                uint32_t off = ((arow + mt * 16) * GSTRIDE + kk + acol0) * 2;
                ldsm4(ah[mt], base + 0 * GTILE_B + off);
                ldsm4(al[mt], base + 1 * GTILE_B + off);
            }
#pragma unroll
            for (int nt = 0; nt < 4; ++nt) {
                uint32_t off = ((brow + nt * 8) * GSTRIDE + kk + bcol0) * 2;
                ldsm2(bh[nt], base + 2 * GTILE_B + off);
                ldsm2(bl[nt], base + 3 * GTILE_B + off);
            }
#pragma unroll
            for (int mt = 0; mt < 4; ++mt)
#pragma unroll
                for (int nt = 0; nt < 4; ++nt) {
                    mma16816(acc[mt][nt], ah[mt], bh[nt]);
                    mma16816(acc[mt][nt], ah[mt], bl[nt]);
                    mma16816(acc[mt][nt], al[mt], bh[nt]);
                }
        }
        __syncthreads();
    }

#pragma unroll
    for (int mt = 0; mt < 4; ++mt) {
        const int row = (int)by + wm * 64 + mt * 16 + (lane >> 2);
#pragma unroll
        for (int nt = 0; nt < 4; ++nt) {
            const int col = (int)bx + wn * 32 + nt * 8 + (lane & 3) * 2;
            *(float2*)(C + (size_t)row * N + col)       = make_float2(acc[mt][nt][0], acc[mt][nt][1]);
            *(float2*)(C + (size_t)(row + 8) * N + col) = make_float2(acc[mt][nt][2], acc[mt][nt][3]);
        }
    }
}

// ---------------- RoPE + RMS-norm -> bf16 hi/lo splits (strided source) ----------------
__global__ void rope_rms_split(const float* __restrict__ buf, int rstride, int coloff, int nh,
                               __nv_bfloat16* __restrict__ oh,
                               __nv_bfloat16* __restrict__ ol,
                               const float* __restrict__ cosb,
                               const float* __restrict__ sinb)
{
    const int row = blockIdx.x;          // = bs*nh + h
    const int bs  = row / nh;
    const int hh  = row - bs * nh;
    const int s   = bs % S_;
    const float* p = buf + (size_t)bs * rstride + coloff + hh * D_;
    const int t  = threadIdx.x;
    const int dh = t & 63;

    float c  = cosb[s * 64 + dh];
    float sn = sinb[s * 64 + dh];
    float x1 = p[dh];
    float x2 = p[dh + 64];
    float val = (t < 64) ? (x1 * c + x2 * sn) : (x2 * c - x1 * sn);

    float sq = val * val;
#pragma unroll
    for (int o = 16; o; o >>= 1) sq += __shfl_xor_sync(0xffffffffu, sq, o);
    __shared__ float red[4];
    if ((t & 31) == 0) red[t >> 5] = sq;
    __syncthreads();
    float total = red[0] + red[1] + red[2] + red[3];
    float y = val * rsqrtf(total * (1.0f / 128.0f) + 1.1920929e-7f);
    __nv_bfloat16 h = __float2bfloat16(y);
    oh[(size_t)row * D_ + t] = h;
    ol[(size_t)row * D_ + t] = __float2bfloat16(y - __bfloat162float(h));
}

// ---------------- windowed-causal flash attention (split-bf16 HMMA) ----------------
// block: 128 queries x 1 head; 8 warps; double-buffered K/V tiles of 64 keys.
#define LDH 136
#define KV_TILE_B (64 * LDH * 2)     // 17408
#define Q_TILE_B  (128 * LDH * 2)    // 34816
#define ATTN_SMEM (2 * Q_TILE_B + 8 * KV_TILE_B)   // 208896

__global__ void __launch_bounds__(256, 1)
attn_mma(const __nv_bfloat16* __restrict__ qh, const __nv_bfloat16* __restrict__ ql,
         const __nv_bfloat16* __restrict__ kh, const __nv_bfloat16* __restrict__ kl,
         const __nv_bfloat16* __restrict__ vh, const __nv_bfloat16* __restrict__ vl,
         __nv_bfloat16* __restrict__ aoh, __nv_bfloat16* __restrict__ aol)
{
    extern __shared__ char smem[];
    const uint32_t sb  = smem_u32(smem);
    const uint32_t QH  = sb, QL = sb + Q_TILE_B;
    const uint32_t kvb = sb + 2 * Q_TILE_B;

    const int mblk = blockIdx.x, h = blockIdx.y, b = blockIdx.z;
    const int q0 = mblk * 128;
    const int hk = h >> 2;
    const int tid = threadIdx.x, lane = tid & 31, w = tid >> 5;

    // Q tile load (once)
    for (int i = tid; i < 2048; i += 256) {
        int r = i >> 4, c = (i & 15) * 8;
        size_t g = ((size_t)(b * S_ + q0 + r) * H_ + h) * D_ + c;
        uint32_t o = (uint32_t)(r * LDH + c) * 2;
        cpasync16(QH + o, qh + g);
        cpasync16(QL + o, ql + g);
    }
    CP_COMMIT();

    float o_acc[16][4];
#pragma unroll
    for (int nt = 0; nt < 16; ++nt)
#pragma unroll
        for (int e = 0; e < 4; ++e) o_acc[nt][e] = 0.f;
    float m_lo = -1e30f, m_hi = -1e30f, l_lo = 0.f, l_hi = 0.f;

    const float scale = 0.08838834764831845f;
    // earliest key tile: floor((q0 - (WIN-1)) / 64)
    const int t_first = (2 * mblk - 16 > 0) ? (2 * mblk - 16) : 0;
    const int t_last  = 2 * mblk + 1;
    const int lane2 = lane & 15;

    auto issue_kv = [&](int t, int s) {
        const uint32_t base = kvb + (uint32_t)s * 4 * KV_TILE_B;
        for (int i = tid; i < 1024; i += 256) {
            int r = i >> 4, c = (i & 15) * 8;
            size_t g = ((size_t)(b * S_ + t * 64 + r) * KV_ + hk) * D_ + c;
            uint32_t o = (uint32_t)(r * LDH + c) * 2;
            cpasync16(base + 0 * KV_TILE_B + o, kh + g);
            cpasync16(base + 1 * KV_TILE_B + o, kl + g);
            cpasync16(base + 2 * KV_TILE_B + o, vh + g);
            cpasync16(base + 3 * KV_TILE_B + o, vl + g);
        }
    };
    issue_kv(t_first, t_first & 1);
    CP_COMMIT();

    const uint32_t a_off = (uint32_t)((w * 16 + (lane & 15)) * LDH + (lane >> 4) * 8) * 2;
    const int i_lo = q0 + w * 16 + (lane >> 2);
    const int i_hi = i_lo + 8;

    for (int t = t_first; t <= t_last; ++t) {
        const int j0 = t * 64;
        __syncthreads();                       // stage being overwritten is free
        if (t < t_last) { issue_kv(t + 1, (t + 1) & 1); CP_COMMIT(); CP_WAIT(1); }
        else            { CP_WAIT(0); }
        __syncthreads();

        const uint32_t KHb = kvb + (uint32_t)(t & 1) * 4 * KV_TILE_B;
        const uint32_t KLb = KHb + KV_TILE_B;
        const uint32_t VHb = KHb + 2 * KV_TILE_B;
        const uint32_t VLb = KHb + 3 * KV_TILE_B;

        // ---- S = Q K^T (split) ----
        float s[8][4];
#pragma unroll
        for (int nt = 0; nt < 8; ++nt)
#pragma unroll
            for (int e = 0; e < 4; ++e) s[nt][e] = 0.f;

#pragma unroll
        for (int kk = 0; kk < 128; kk += 16) {
            uint32_t ah[4], al[4];
            ldsm4(ah, QH + a_off + kk * 2);
            ldsm4(al, QL + a_off + kk * 2);
#pragma unroll
            for (int nt = 0; nt < 8; ++nt) {
                uint32_t off = (uint32_t)((nt * 8 + (lane2 & 7)) * LDH + kk + ((lane2 >> 3) & 1) * 8) * 2;
                uint32_t bh2[2], bl2[2];
                ldsm2(bh2, KHb + off);
                ldsm2(bl2, KLb + off);
                mma16816(s[nt], ah, bh2);
                mma16816(s[nt], ah, bl2);
                mma16816(s[nt], al, bh2);
            }
        }

        // ---- masked online softmax ----
        float mx_lo = -1e30f, mx_hi = -1e30f;
#pragma unroll
        for (int nt = 0; nt < 8; ++nt) {
            int jb = j0 + nt * 8 + (lane & 3) * 2;
            bool v0 = (jb     <= i_lo) && (i_lo - jb     < WIN_);
            bool v1 = (jb + 1 <= i_lo) && (i_lo - jb - 1 < WIN_);
            bool v2 = (jb     <= i_hi) && (i_hi - jb     < WIN_);
            bool v3 = (jb + 1 <= i_hi) && (i_hi - jb - 1 < WIN_);
            s[nt][0] = v0 ? s[nt][0] * scale : -1e30f;
            s[nt][1] = v1 ? s[nt][1] * scale : -1e30f;
            s[nt][2] = v2 ? s[nt][2] * scale : -1e30f;
            s[nt][3] = v3 ? s[nt][3] * scale : -1e30f;
            mx_lo = fmaxf(mx_lo, fmaxf(s[nt][0], s[nt][1]));
            mx_hi = fmaxf(mx_hi, fmaxf(s[nt][2], s[nt][3]));
        }
        mx_lo = fmaxf(mx_lo, __shfl_xor_sync(0xffffffffu, mx_lo, 1));
        mx_lo = fmaxf(mx_lo, __shfl_xor_sync(0xffffffffu, mx_lo, 2));
        mx_hi = fmaxf(mx_hi, __shfl_xor_sync(0xffffffffu, mx_hi, 1));
        mx_hi = fmaxf(mx_hi, __shfl_xor_sync(0xffffffffu, mx_hi, 2));

        float mn_lo = fmaxf(m_lo, mx_lo), mn_hi = fmaxf(m_hi, mx_hi);
        float al_lo = __expf(m_lo - mn_lo), al_hi = __expf(m_hi - mn_hi);
        float sum_lo = 0.f, sum_hi = 0.f;
#pragma unroll
        for (int nt = 0; nt < 8; ++nt) {
            s[nt][0] = __expf(s[nt][0] - mn_lo);
            s[nt][1] = __expf(s[nt][1] - mn_lo);
            s[nt][2] = __expf(s[nt][2] - mn_hi);
            s[nt][3] = __expf(s[nt][3] - mn_hi);
            sum_lo += s[nt][0] + s[nt][1];
            sum_hi += s[nt][2] + s[nt][3];
        }
        sum_lo += __shfl_xor_sync(0xffffffffu, sum_lo, 1);
        sum_lo += __shfl_xor_sync(0xffffffffu, sum_lo, 2);
        sum_hi += __shfl_xor_sync(0xffffffffu, sum_hi, 1);
        sum_hi += __shfl_xor_sync(0xffffffffu, sum_hi, 2);
        l_lo = l_lo * al_lo + sum_lo;  m_lo = mn_lo;
        l_hi = l_hi * al_hi + sum_hi;  m_hi = mn_hi;
#pragma unroll
        for (int nt = 0; nt < 16; ++nt) {
            o_acc[nt][0] *= al_lo; o_acc[nt][1] *= al_lo;
            o_acc[nt][2] *= al_hi; o_acc[nt][3] *= al_hi;
        }

        // ---- O += P V (split) ----
#pragma unroll
        for (int kc = 0; kc < 4; ++kc) {
            uint32_t aph[4], apl[4];
            split2(s[2*kc][0],   s[2*kc][1],   aph[0], apl[0]);
            split2(s[2*kc][2],   s[2*kc][3],   aph[1], apl[1]);
            split2(s[2*kc+1][0], s[2*kc+1][1], aph[2], apl[2]);
            split2(s[2*kc+1][2], s[2*kc+1][3], aph[3], apl[3]);

            uint32_t vr = (uint32_t)(kc * 16 + (lane & 7) + ((lane >> 3) & 1) * 8) * LDH
                        + (uint32_t)((lane >> 4) * 8);
#pragma unroll
            for (int dt = 0; dt < 8; ++dt) {
                uint32_t off = (vr + dt * 16) * 2;
                uint32_t bvh[4], bvl[4];
                ldsm4t(bvh, VHb + off);
                ldsm4t(bvl, VLb + off);
                mma16816(o_acc[2*dt],   aph, bvh);
                mma16816(o_acc[2*dt],   aph, bvl);
                mma16816(o_acc[2*dt],   apl, bvh);
                mma16816(o_acc[2*dt+1], aph, bvh + 2);
                mma16816(o_acc[2*dt+1], aph, bvl + 2);
                mma16816(o_acc[2*dt+1], apl, bvh + 2);
            }
        }
    }

    // ---- epilogue ----
    float inv_lo = 1.0f / l_lo, inv_hi = 1.0f / l_hi;
#pragma unroll
    for (int nt = 0; nt < 16; ++nt) {
        int c = nt * 8 + (lane & 3) * 2;
        size_t glo = ((size_t)(b * S_ + i_lo) * H_ + h) * D_ + c;
        size_t ghi = ((size_t)(b * S_ + i_hi) * H_ + h) * D_ + c;
        uint32_t hh, ll;
        split2(o_acc[nt][0] * inv_lo, o_acc[nt][1] * inv_lo, hh, ll);
        *(uint32_t*)(aoh + glo) = hh;
        *(uint32_t*)(aol + glo) = ll;
        split2(o_acc[nt][2] * inv_hi, o_acc[nt][3] * inv_hi, hh, ll);
        *(uint32_t*)(aoh + ghi) = hh;
        *(uint32_t*)(aol + ghi) = ll;
    }
}

// ---------------- launch ----------------
extern "C" void kernel_launch(void* const* d_in, const int* in_sizes, int n_in,
                              void* d_out, int out_size)
{
    (void)in_sizes; (void)n_in; (void)out_size;
    const float* x    = (const float*)d_in[0];
    const float* cosb = (const float*)d_in[1];
    const float* sinb = (const float*)d_in[2];
    const float* Wq   = (const float*)d_in[3];
    const float* Wk   = (const float*)d_in[4];
    const float* Wv   = (const float*)d_in[5];
    const float* Wo   = (const float*)d_in[6];
    float* out = (float*)d_out;

    float* qkv;
    cudaGetSymbolAddress((void**)&qkv, g_qkv);
    __nv_bfloat16 *xh, *xl, *wph, *wpl, *woh, *wol, *aoh, *aol;
    __nv_bfloat16 *qh, *ql, *kh, *kl, *vh, *vl;
    cudaGetSymbolAddress((void**)&xh,  g_xh);  cudaGetSymbolAddress((void**)&xl,  g_xl);
    cudaGetSymbolAddress((void**)&wph, g_wph); cudaGetSymbolAddress((void**)&wpl, g_wpl);
    cudaGetSymbolAddress((void**)&woh, g_woh); cudaGetSymbolAddress((void**)&wol, g_wol);
    cudaGetSymbolAddress((void**)&aoh, g_aoh); cudaGetSymbolAddress((void**)&aol, g_aol);
    cudaGetSymbolAddress((void**)&qh,  g_qh);  cudaGetSymbolAddress((void**)&ql,  g_ql);
    cudaGetSymbolAddress((void**)&kh,  g_kh);  cudaGetSymbolAddress((void**)&kl,  g_kl);
    cudaGetSymbolAddress((void**)&vh,  g_vh);  cudaGetSymbolAddress((void**)&vl,  g_vl);

    const int M = MSZ_;   // 4096
    cudaFuncSetAttribute(gemm_mma, cudaFuncAttributeMaxDynamicSharedMemorySize, GEMM_SMEM);
    cudaFuncSetAttribute(attn_mma, cudaFuncAttributeMaxDynamicSharedMemorySize, ATTN_SMEM);

    auto SPLIT = [](const float* src, __nv_bfloat16* h, __nv_bfloat16* l, size_t n) {
        int n4 = (int)(n / 4);
        split_bf16<<<(n4 + 255) / 256, 256>>>(src, h, l, n4);
    };

    // splits: x, packed W(q|k|v), Wo
    SPLIT(x,  xh, xl, (size_t)M * E_);
    SPLIT(Wq, wph,                         wpl,                         (size_t)NQ_ * E_);
    SPLIT(Wk, wph + (size_t)NQ_ * E_,      wpl + (size_t)NQ_ * E_,      (size_t)NKV_ * E_);
    SPLIT(Wv, wph + (size_t)(NQ_+NKV_)*E_, wpl + (size_t)(NQ_+NKV_)*E_, (size_t)NKV_ * E_);
    SPLIT(Wo, woh, wol, (size_t)E_ * NQ_);

    // fused QKV projection
    gemm_mma<<<dim3(NQKV_ / 128, M / 128), 256, GEMM_SMEM>>>(xh, xl, wph, wpl, qkv, NQKV_, E_);

    // v split + rope/rms splits for q, k
    split_v<<<(M * 128 + 255) / 256, 256>>>(qkv, vh, vl);
    rope_rms_split<<<M * H_,  128>>>(qkv, NQKV_, 0,   H_,  qh, ql, cosb, sinb);
    rope_rms_split<<<M * KV_, 128>>>(qkv, NQKV_, NQ_, KV_, kh, kl, cosb, sinb);

    // attention (128-query CTAs, double-buffered KV)
    attn_mma<<<dim3(S_ / 128, H_, B_), 256, ATTN_SMEM>>>(qh, ql, kh, kl, vh, vl, aoh, aol);

    // output projection
    gemm_mma<<<dim3(E_ / 128, M / 128), 256, GEMM_SMEM>>>(aoh, aol, woh, wol, out, E_, NQ_);
}

// round 10
// speedup vs baseline: 4.8923x; 1.8719x over previous
#include <cuda_runtime.h>
#include <cuda_bf16.h>
#include <cuda_fp16.h>
#include <cstdint>

#define B_   2
#define S_   2048
#define E_   2048
#define H_   16
#define KV_  4
#define D_   128
#define WIN_ 1024

#define MSZ_ (B_ * S_)     // 4096
#define NQ_  (H_ * D_)     // 2048
#define NKV_ (KV_ * D_)    // 512
#define NQKV_ (NQ_ + 2 * NKV_)   // 3072

// ---------------- scratch ----------------
__device__ float g_qkv[(size_t)MSZ_ * NQKV_];   // packed [M, q|k|v]

__device__ __half g_x16 [(size_t)MSZ_ * E_];
__device__ __half g_wp16[(size_t)NQKV_ * E_];   // packed Wq|Wk|Wv
__device__ __half g_wo16[(size_t)E_ * NQ_];
__device__ __half g_ao16[(size_t)MSZ_ * NQ_];

__device__ __nv_bfloat16 g_qh [(size_t)MSZ_ * NQ_],  g_ql [(size_t)MSZ_ * NQ_];
__device__ __nv_bfloat16 g_kh [(size_t)MSZ_ * NKV_], g_kl [(size_t)MSZ_ * NKV_];
__device__ __nv_bfloat16 g_vh [(size_t)MSZ_ * NKV_], g_vl [(size_t)MSZ_ * NKV_];

// ---------------- helpers ----------------
__device__ __forceinline__ uint32_t smem_u32(const void* p) {
    uint32_t a;
    asm("{ .reg .u64 t; cvta.to.shared.u64 t, %1; cvt.u32.u64 %0, t; }" : "=r"(a) : "l"(p));
    return a;
}
__device__ __forceinline__ void cpasync16(uint32_t dst, const void* src) {
    asm volatile("cp.async.cg.shared.global [%0], [%1], 16;" :: "r"(dst), "l"(src));
}
#define CP_COMMIT()  asm volatile("cp.async.commit_group;" ::: "memory")
#define CP_WAIT(n)   asm volatile("cp.async.wait_group %0;" :: "n"(n) : "memory")

__device__ __forceinline__ void ldsm4(uint32_t* r, uint32_t addr) {
    asm volatile("ldmatrix.sync.aligned.m8n8.x4.shared.b16 {%0,%1,%2,%3}, [%4];"
                 : "=r"(r[0]), "=r"(r[1]), "=r"(r[2]), "=r"(r[3]) : "r"(addr));
}
__device__ __forceinline__ void ldsm2(uint32_t* r, uint32_t addr) {
    asm volatile("ldmatrix.sync.aligned.m8n8.x2.shared.b16 {%0,%1}, [%2];"
                 : "=r"(r[0]), "=r"(r[1]) : "r"(addr));
}
__device__ __forceinline__ void ldsm4t(uint32_t* r, uint32_t addr) {
    asm volatile("ldmatrix.sync.aligned.m8n8.x4.trans.shared.b16 {%0,%1,%2,%3}, [%4];"
                 : "=r"(r[0]), "=r"(r[1]), "=r"(r[2]), "=r"(r[3]) : "r"(addr));
}
__device__ __forceinline__ void mma16816(float* d, const uint32_t* a, const uint32_t* b) {
    asm volatile("mma.sync.aligned.m16n8k16.row.col.f32.bf16.bf16.f32 "
                 "{%0,%1,%2,%3}, {%4,%5,%6,%7}, {%8,%9}, {%0,%1,%2,%3};"
                 : "+f"(d[0]), "+f"(d[1]), "+f"(d[2]), "+f"(d[3])
                 : "r"(a[0]), "r"(a[1]), "r"(a[2]), "r"(a[3]), "r"(b[0]), "r"(b[1]));
}
__device__ __forceinline__ void mma16816h(float* d, const uint32_t* a, const uint32_t* b) {
    asm volatile("mma.sync.aligned.m16n8k16.row.col.f32.f16.f16.f32 "
                 "{%0,%1,%2,%3}, {%4,%5,%6,%7}, {%8,%9}, {%0,%1,%2,%3};"
                 : "+f"(d[0]), "+f"(d[1]), "+f"(d[2]), "+f"(d[3])
                 : "r"(a[0]), "r"(a[1]), "r"(a[2]), "r"(a[3]), "r"(b[0]), "r"(b[1]));
}
__device__ __forceinline__ void split2(float a, float b, uint32_t& hi, uint32_t& lo) {
    __nv_bfloat16 ha = __float2bfloat16(a), hb = __float2bfloat16(b);
    __nv_bfloat162 h2; h2.x = ha; h2.y = hb;
    hi = *reinterpret_cast<uint32_t*>(&h2);
    __nv_bfloat162 l2;
    l2.x = __float2bfloat16(a - __bfloat162float(ha));
    l2.y = __float2bfloat16(b - __bfloat162float(hb));
    lo = *reinterpret_cast<uint32_t*>(&l2);
}

// ---------------- fp32 -> fp16 convert ----------------
__global__ void to_fp16(const float* __restrict__ x, __half* __restrict__ y, int n4)
{
    int i = blockIdx.x * blockDim.x + threadIdx.x;
    if (i >= n4) return;
    float4 v = ((const float4*)x)[i];
    ((__half2*)y)[i * 2]     = __floats2half2_rn(v.x, v.y);
    ((__half2*)y)[i * 2 + 1] = __floats2half2_rn(v.z, v.w);
}

// split V out of the packed QKV buffer (strided read; V at col NQ_+NKV_)
__global__ void split_v(const float* __restrict__ qkv,
                        __nv_bfloat16* __restrict__ vh, __nv_bfloat16* __restrict__ vl)
{
    int i = blockIdx.x * blockDim.x + threadIdx.x;   // over MSZ_*128 float4 chunks
    if (i >= MSZ_ * 128) return;
    int row = i >> 7, c4 = (i & 127) * 4;
    float4 v = *(const float4*)(qkv + (size_t)row * NQKV_ + (NQ_ + NKV_) + c4);
    uint32_t h0, l0, h1, l1;
    split2(v.x, v.y, h0, l0);
    split2(v.z, v.w, h1, l1);
    size_t o = ((size_t)row * NKV_ + c4) >> 1;
    ((uint32_t*)vh)[o]     = h0;
    ((uint32_t*)vh)[o + 1] = h1;
    ((uint32_t*)vl)[o]     = l0;
    ((uint32_t*)vl)[o + 1] = l1;
}

// ---------------- single-pass fp16 HMMA GEMM (4-stage cp.async pipeline) ----------------
// C[M,N] = A[M,K] @ B[N,K]^T, fp32 accum. 128x128 CTA tile, K-step 32.
#define GSTRIDE 40
#define GTILE_B (128 * GSTRIDE * 2)          // 10240
#define GSTAGE_B (2 * GTILE_B)               // 20480 (A + B)
#define GEMM_SMEM (4 * GSTAGE_B)             // 81920 -> 2 CTA/SM

__global__ void __launch_bounds__(256)
gemm_f16(const __half* __restrict__ A, const __half* __restrict__ Bw,
         float* __restrict__ C, int N, int K)
{
    extern __shared__ char smem[];
    const uint32_t sb = smem_u32(smem);

    const int tid  = threadIdx.x;
    const int lane = tid & 31, warp = tid >> 5;
    const int wm   = warp >> 2;
    const int wn   = warp & 3;
    const size_t by = (size_t)blockIdx.y * 128;
    const size_t bx = (size_t)blockIdx.x * 128;

    const __half* srcA = A  + by * K;
    const __half* srcB = Bw + bx * K;

    const int r0 = tid >> 2,  c0 = (tid & 3);
    const int r1 = r0 + 64;

    auto issue = [&](int kt, int s) {
        const uint32_t base = sb + (uint32_t)s * GSTAGE_B;
        cpasync16(base + (r0 * GSTRIDE + c0 * 8) * 2, srcA + (size_t)r0 * K + kt * 32 + c0 * 8);
        cpasync16(base + (r1 * GSTRIDE + c0 * 8) * 2, srcA + (size_t)r1 * K + kt * 32 + c0 * 8);
        cpasync16(base + GTILE_B + (r0 * GSTRIDE + c0 * 8) * 2, srcB + (size_t)r0 * K + kt * 32 + c0 * 8);
        cpasync16(base + GTILE_B + (r1 * GSTRIDE + c0 * 8) * 2, srcB + (size_t)r1 * K + kt * 32 + c0 * 8);
    };

    float acc[4][4][4];
#pragma unroll
    for (int mt = 0; mt < 4; ++mt)
#pragma unroll
        for (int nt = 0; nt < 4; ++nt)
#pragma unroll
            for (int e = 0; e < 4; ++e) acc[mt][nt][e] = 0.f;

    const int l2 = lane & 15;
    const int arow = wm * 64 + (lane & 15);
    const int acol0 = (lane >> 4) * 8;
    const int brow = wn * 32 + (l2 & 7);
    const int bcol0 = (l2 >> 3) * 8;

    const int KT = K / 32;
    for (int p = 0; p < 3 && p < KT; ++p) { issue(p, p & 3); CP_COMMIT(); }

    for (int kt = 0; kt < KT; ++kt) {
        if (kt + 2 < KT)      CP_WAIT(2);
        else if (kt + 1 < KT) CP_WAIT(1);
        else                  CP_WAIT(0);
        __syncthreads();
        if (kt + 3 < KT) { issue(kt + 3, (kt + 3) & 3); CP_COMMIT(); }

        const uint32_t base = sb + (uint32_t)(kt & 3) * GSTAGE_B;
#pragma unroll
        for (int kk = 0; kk < 32; kk += 16) {
            uint32_t af[4][4], bf[4][2];
#pragma unroll
            for (int mt = 0; mt < 4; ++mt)
                ldsm4(af[mt], base + ((arow + mt * 16) * GSTRIDE + kk + acol0) * 2);
#pragma unroll
            for (int nt = 0; nt < 4; ++nt)
                ldsm2(bf[nt], base + GTILE_B + ((brow + nt * 8) * GSTRIDE + kk + bcol0) * 2);
#pragma unroll
            for (int mt = 0; mt < 4; ++mt)
#pragma unroll
                for (int nt = 0; nt < 4; ++nt)
                    mma16816h(acc[mt][nt], af[mt], bf[nt]);
        }
    }

#pragma unroll
    for (int mt = 0; mt < 4; ++mt) {
        const int row = (int)by + wm * 64 + mt * 16 + (lane >> 2);
#pragma unroll
        for (int nt = 0; nt < 4; ++nt) {
            const int col = (int)bx + wn * 32 + nt * 8 + (lane & 3) * 2;
            *(float2*)(C + (size_t)row * N + col)       = make_float2(acc[mt][nt][0], acc[mt][nt][1]);
            *(float2*)(C + (size_t)(row + 8) * N + col) = make_float2(acc[mt][nt][2], acc[mt][nt][3]);
        }
    }
}

// ---------------- RoPE + RMS-norm -> bf16 hi/lo splits (strided source) ----------------
__global__ void rope_rms_split(const float* __restrict__ buf, int rstride, int coloff, int nh,
                               __nv_bfloat16* __restrict__ oh,
                               __nv_bfloat16* __restrict__ ol,
                               const float* __restrict__ cosb,
                               const float* __restrict__ sinb)
{
    const int row = blockIdx.x;          // = bs*nh + h
    const int bs  = row / nh;
    const int hh  = row - bs * nh;
    const int s   = bs % S_;
    const float* p = buf + (size_t)bs * rstride + coloff + hh * D_;
    const int t  = threadIdx.x;
    const int dh = t & 63;

    float c  = cosb[s * 64 + dh];
    float sn = sinb[s * 64 + dh];
    float x1 = p[dh];
    float x2 = p[dh + 64];
    float val = (t < 64) ? (x1 * c + x2 * sn) : (x2 * c - x1 * sn);

    float sq = val * val;
#pragma unroll
    for (int o = 16; o; o >>= 1) sq += __shfl_xor_sync(0xffffffffu, sq, o);
    __shared__ float red[4];
    if ((t & 31) == 0) red[t >> 5] = sq;
    __syncthreads();
    float total = red[0] + red[1] + red[2] + red[3];
    float y = val * rsqrtf(total * (1.0f / 128.0f) + 1.1920929e-7f);
    __nv_bfloat16 h = __float2bfloat16(y);
    oh[(size_t)row * D_ + t] = h;
    ol[(size_t)row * D_ + t] = __float2bfloat16(y - __bfloat162float(h));
}

// ---------------- windowed-causal flash attention (split-bf16 HMMA) ----------------
// block: 128 queries x 1 head; 8 warps; double-buffered K/V tiles of 64 keys.
#define LDH 136
#define KV_TILE_B (64 * LDH * 2)     // 17408
#define Q_TILE_B  (128 * LDH * 2)    // 34816
#define ATTN_SMEM (2 * Q_TILE_B + 8 * KV_TILE_B)   // 208896

__global__ void __launch_bounds__(256, 1)
attn_mma(const __nv_bfloat16* __restrict__ qh, const __nv_bfloat16* __restrict__ ql,
         const __nv_bfloat16* __restrict__ kh, const __nv_bfloat16* __restrict__ kl,
         const __nv_bfloat16* __restrict__ vh, const __nv_bfloat16* __restrict__ vl,
         __half* __restrict__ ao)
{
    extern __shared__ char smem[];
    const uint32_t sb  = smem_u32(smem);
    const uint32_t QH  = sb, QL = sb + Q_TILE_B;
    const uint32_t kvb = sb + 2 * Q_TILE_B;

    const int mblk = blockIdx.x, h = blockIdx.y, b = blockIdx.z;
    const int q0 = mblk * 128;
    const int hk = h >> 2;
    const int tid = threadIdx.x, lane = tid & 31, w = tid >> 5;

    // Q tile load (once)
    for (int i = tid; i < 2048; i += 256) {
        int r = i >> 4, c = (i & 15) * 8;
        size_t g = ((size_t)(b * S_ + q0 + r) * H_ + h) * D_ + c;
        uint32_t o = (uint32_t)(r * LDH + c) * 2;
        cpasync16(QH + o, qh + g);
        cpasync16(QL + o, ql + g);
    }
    CP_COMMIT();

    float o_acc[16][4];
#pragma unroll
    for (int nt = 0; nt < 16; ++nt)
#pragma unroll
        for (int e = 0; e < 4; ++e) o_acc[nt][e] = 0.f;
    float m_lo = -1e30f, m_hi = -1e30f, l_lo = 0.f, l_hi = 0.f;

    const float scale = 0.08838834764831845f;
    const int t_first = (2 * mblk - 16 > 0) ? (2 * mblk - 16) : 0;
    const int t_last  = 2 * mblk + 1;
    const int lane2 = lane & 15;

    auto issue_kv = [&](int t, int s) {
        const uint32_t base = kvb + (uint32_t)s * 4 * KV_TILE_B;
        for (int i = tid; i < 1024; i += 256) {
            int r = i >> 4, c = (i & 15) * 8;
            size_t g = ((size_t)(b * S_ + t * 64 + r) * KV_ + hk) * D_ + c;
            uint32_t o = (uint32_t)(r * LDH + c) * 2;
            cpasync16(base + 0 * KV_TILE_B + o, kh + g);
            cpasync16(base + 1 * KV_TILE_B + o, kl + g);
            cpasync16(base + 2 * KV_TILE_B + o, vh + g);
            cpasync16(base + 3 * KV_TILE_B + o, vl + g);
        }
    };
    issue_kv(t_first, t_first & 1);
    CP_COMMIT();

    const uint32_t a_off = (uint32_t)((w * 16 + (lane & 15)) * LDH + (lane >> 4) * 8) * 2;
    const int i_lo = q0 + w * 16 + (lane >> 2);
    const int i_hi = i_lo + 8;

    for (int t = t_first; t <= t_last; ++t) {
        const int j0 = t * 64;
        __syncthreads();                       // stage being overwritten is free
        if (t < t_last) { issue_kv(t + 1, (t + 1) & 1); CP_COMMIT(); CP_WAIT(1); }
        else            { CP_WAIT(0); }
        __syncthreads();

        const uint32_t KHb = kvb + (uint32_t)(t & 1) * 4 * KV_TILE_B;
        const uint32_t KLb = KHb + KV_TILE_B;
        const uint32_t VHb = KHb + 2 * KV_TILE_B;
        const uint32_t VLb = KHb + 3 * KV_TILE_B;

        // ---- S = Q K^T (split) ----
        float s[8][4];
#pragma unroll
        for (int nt = 0; nt < 8; ++nt)
#pragma unroll
            for (int e = 0; e < 4; ++e) s[nt][e] = 0.f;

#pragma unroll
        for (int kk = 0; kk < 128; kk += 16) {
            uint32_t ah[4], al[4];
            ldsm4(ah, QH + a_off + kk * 2);
            ldsm4(al, QL + a_off + kk * 2);
#pragma unroll
            for (int nt = 0; nt < 8; ++nt) {
                uint32_t off = (uint32_t)((nt * 8 + (lane2 & 7)) * LDH + kk + ((lane2 >> 3) & 1) * 8) * 2;
                uint32_t bh2[2], bl2[2];
                ldsm2(bh2, KHb + off);
                ldsm2(bl2, KLb + off);
                mma16816(s[nt], ah, bh2);
                mma16816(s[nt], ah, bl2);
                mma16816(s[nt], al, bh2);
            }
        }

        // ---- masked online softmax ----
        float mx_lo = -1e30f, mx_hi = -1e30f;
#pragma unroll
        for (int nt = 0; nt < 8; ++nt) {
            int jb = j0 + nt * 8 + (lane & 3) * 2;
            bool v0 = (jb     <= i_lo) && (i_lo - jb     < WIN_);
            bool v1 = (jb + 1 <= i_lo) && (i_lo - jb - 1 < WIN_);
            bool v2 = (jb     <= i_hi) && (i_hi - jb     < WIN_);
            bool v3 = (jb + 1 <= i_hi) && (i_hi - jb - 1 < WIN_);
            s[nt][0] = v0 ? s[nt][0] * scale : -1e30f;
            s[nt][1] = v1 ? s[nt][1] * scale : -1e30f;
            s[nt][2] = v2 ? s[nt][2] * scale : -1e30f;
            s[nt][3] = v3 ? s[nt][3] * scale : -1e30f;
            mx_lo = fmaxf(mx_lo, fmaxf(s[nt][0], s[nt][1]));
            mx_hi = fmaxf(mx_hi, fmaxf(s[nt][2], s[nt][3]));
        }
        mx_lo = fmaxf(mx_lo, __shfl_xor_sync(0xffffffffu, mx_lo, 1));
        mx_lo = fmaxf(mx_lo, __shfl_xor_sync(0xffffffffu, mx_lo, 2));
        mx_hi = fmaxf(mx_hi, __shfl_xor_sync(0xffffffffu, mx_hi, 1));
        mx_hi = fmaxf(mx_hi, __shfl_xor_sync(0xffffffffu, mx_hi, 2));

        float mn_lo = fmaxf(m_lo, mx_lo), mn_hi = fmaxf(m_hi, mx_hi);
        float al_lo = __expf(m_lo - mn_lo), al_hi = __expf(m_hi - mn_hi);
        float sum_lo = 0.f, sum_hi = 0.f;
#pragma unroll
        for (int nt = 0; nt < 8; ++nt) {
            s[nt][0] = __expf(s[nt][0] - mn_lo);
            s[nt][1] = __expf(s[nt][1] - mn_lo);
            s[nt][2] = __expf(s[nt][2] - mn_hi);
            s[nt][3] = __expf(s[nt][3] - mn_hi);
            sum_lo += s[nt][0] + s[nt][1];
            sum_hi += s[nt][2] + s[nt][3];
        }
        sum_lo += __shfl_xor_sync(0xffffffffu, sum_lo, 1);
        sum_lo += __shfl_xor_sync(0xffffffffu, sum_lo, 2);
        sum_hi += __shfl_xor_sync(0xffffffffu, sum_hi, 1);
        sum_hi += __shfl_xor_sync(0xffffffffu, sum_hi, 2);
        l_lo = l_lo * al_lo + sum_lo;  m_lo = mn_lo;
        l_hi = l_hi * al_hi + sum_hi;  m_hi = mn_hi;
#pragma unroll
        for (int nt = 0; nt < 16; ++nt) {
            o_acc[nt][0] *= al_lo; o_acc[nt][1] *= al_lo;
            o_acc[nt][2] *= al_hi; o_acc[nt][3] *= al_hi;
        }

        // ---- O += P V (split) ----
#pragma unroll
        for (int kc = 0; kc < 4; ++kc) {
            uint32_t aph[4], apl[4];
            split2(s[2*kc][0],   s[2*kc][1],   aph[0], apl[0]);
            split2(s[2*kc][2],   s[2*kc][3],   aph[1], apl[1]);
            split2(s[2*kc+1][0], s[2*kc+1][1], aph[2], apl[2]);
            split2(s[2*kc+1][2], s[2*kc+1][3], aph[3], apl[3]);

            uint32_t vr = (uint32_t)(kc * 16 + (lane & 7) + ((lane >> 3) & 1) * 8) * LDH
                        + (uint32_t)((lane >> 4) * 8);
#pragma unroll
            for (int dt = 0; dt < 8; ++dt) {
                uint32_t off = (vr + dt * 16) * 2;
                uint32_t bvh[4], bvl[4];
                ldsm4t(bvh, VHb + off);
                ldsm4t(bvl, VLb + off);
                mma16816(o_acc[2*dt],   aph, bvh);
                mma16816(o_acc[2*dt],   aph, bvl);
                mma16816(o_acc[2*dt],   apl, bvh);
                mma16816(o_acc[2*dt+1], aph, bvh + 2);
                mma16816(o_acc[2*dt+1], aph, bvl + 2);
                mma16816(o_acc[2*dt+1], apl, bvh + 2);
            }
        }
    }

    // ---- epilogue: normalize, write fp16 ----
    float inv_lo = 1.0f / l_lo, inv_hi = 1.0f / l_hi;
#pragma unroll
    for (int nt = 0; nt < 16; ++nt) {
        int c = nt * 8 + (lane & 3) * 2;
        size_t glo = ((size_t)(b * S_ + i_lo) * H_ + h) * D_ + c;
        size_t ghi = ((size_t)(b * S_ + i_hi) * H_ + h) * D_ + c;
        *(__half2*)(ao + glo) = __floats2half2_rn(o_acc[nt][0] * inv_lo, o_acc[nt][1] * inv_lo);
        *(__half2*)(ao + ghi) = __floats2half2_rn(o_acc[nt][2] * inv_hi, o_acc[nt][3] * inv_hi);
    }
}

// ---------------- launch ----------------
extern "C" void kernel_launch(void* const* d_in, const int* in_sizes, int n_in,
                              void* d_out, int out_size)
{
    (void)in_sizes; (void)n_in; (void)out_size;
    const float* x    = (const float*)d_in[0];
    const float* cosb = (const float*)d_in[1];
    const float* sinb = (const float*)d_in[2];
    const float* Wq   = (const float*)d_in[3];
    const float* Wk   = (const float*)d_in[4];
    const float* Wv   = (const float*)d_in[5];
    const float* Wo   = (const float*)d_in[6];
    float* out = (float*)d_out;

    float* qkv;
    cudaGetSymbolAddress((void**)&qkv, g_qkv);
    __half *x16, *wp16, *wo16, *ao16;
    __nv_bfloat16 *qh, *ql, *kh, *kl, *vh, *vl;
    cudaGetSymbolAddress((void**)&x16,  g_x16);
    cudaGetSymbolAddress((void**)&wp16, g_wp16);
    cudaGetSymbolAddress((void**)&wo16, g_wo16);
    cudaGetSymbolAddress((void**)&ao16, g_ao16);
    cudaGetSymbolAddress((void**)&qh,  g_qh);  cudaGetSymbolAddress((void**)&ql,  g_ql);
    cudaGetSymbolAddress((void**)&kh,  g_kh);  cudaGetSymbolAddress((void**)&kl,  g_kl);
    cudaGetSymbolAddress((void**)&vh,  g_vh);  cudaGetSymbolAddress((void**)&vl,  g_vl);

    const int M = MSZ_;   // 4096
    cudaFuncSetAttribute(gemm_f16, cudaFuncAttributeMaxDynamicSharedMemorySize, GEMM_SMEM);
    cudaFuncSetAttribute(attn_mma, cudaFuncAttributeMaxDynamicSharedMemorySize, ATTN_SMEM);

    auto CVT = [](const float* src, __half* dst, size_t n) {
        int n4 = (int)(n / 4);
        to_fp16<<<(n4 + 255) / 256, 256>>>(src, dst, n4);
    };

    // fp16 conversions: x, packed W(q|k|v), Wo
    CVT(x,  x16, (size_t)M * E_);
    CVT(Wq, wp16,                          (size_t)NQ_ * E_);
    CVT(Wk, wp16 + (size_t)NQ_ * E_,       (size_t)NKV_ * E_);
    CVT(Wv, wp16 + (size_t)(NQ_+NKV_)*E_,  (size_t)NKV_ * E_);
    CVT(Wo, wo16, (size_t)E_ * NQ_);

    // fused QKV projection (fp16 single-pass)
    gemm_f16<<<dim3(NQKV_ / 128, M / 128), 256, GEMM_SMEM>>>(x16, wp16, qkv, NQKV_, E_);

    // v split + rope/rms splits for q, k (bf16 hi/lo for attention)
    split_v<<<(M * 128 + 255) / 256, 256>>>(qkv, vh, vl);
    rope_rms_split<<<M * H_,  128>>>(qkv, NQKV_, 0,   H_,  qh, ql, cosb, sinb);
    rope_rms_split<<<M * KV_, 128>>>(qkv, NQKV_, NQ_, KV_, kh, kl, cosb, sinb);

    // attention (split-bf16, fp16 output)
    attn_mma<<<dim3(S_ / 128, H_, B_), 256, ATTN_SMEM>>>(qh, ql, kh, kl, vh, vl, ao16);

    // output projection (fp16 single-pass)
    gemm_f16<<<dim3(E_ / 128, M / 128), 256, GEMM_SMEM>>>(ao16, wo16, out, E_, NQ_);
}

// round 11
// speedup vs baseline: 5.9322x; 1.2126x over previous
#include <cuda_runtime.h>
#include <cuda_fp16.h>
#include <cstdint>

#define B_   2
#define S_   2048
#define E_   2048
#define H_   16
#define KV_  4
#define D_   128
#define WIN_ 1024

#define MSZ_ (B_ * S_)     // 4096
#define NQ_  (H_ * D_)     // 2048
#define NKV_ (KV_ * D_)    // 512
#define NQKV_ (NQ_ + 2 * NKV_)   // 3072

// ---------------- scratch ----------------
__device__ float g_qkv[(size_t)MSZ_ * NQKV_];   // packed [M, q|k|v]

__device__ __half g_x16 [(size_t)MSZ_ * E_];
__device__ __half g_wp16[(size_t)NQKV_ * E_];   // packed Wq|Wk|Wv
__device__ __half g_wo16[(size_t)E_ * NQ_];
__device__ __half g_ao16[(size_t)MSZ_ * NQ_];
__device__ __half g_q16 [(size_t)MSZ_ * NQ_];
__device__ __half g_k16 [(size_t)MSZ_ * NKV_];
__device__ __half g_v16 [(size_t)MSZ_ * NKV_];

// ---------------- helpers ----------------
__device__ __forceinline__ uint32_t smem_u32(const void* p) {
    uint32_t a;
    asm("{ .reg .u64 t; cvta.to.shared.u64 t, %1; cvt.u32.u64 %0, t; }" : "=r"(a) : "l"(p));
    return a;
}
__device__ __forceinline__ void cpasync16(uint32_t dst, const void* src) {
    asm volatile("cp.async.cg.shared.global [%0], [%1], 16;" :: "r"(dst), "l"(src));
}
#define CP_COMMIT()  asm volatile("cp.async.commit_group;" ::: "memory")
#define CP_WAIT(n)   asm volatile("cp.async.wait_group %0;" :: "n"(n) : "memory")

__device__ __forceinline__ void ldsm4(uint32_t* r, uint32_t addr) {
    asm volatile("ldmatrix.sync.aligned.m8n8.x4.shared.b16 {%0,%1,%2,%3}, [%4];"
                 : "=r"(r[0]), "=r"(r[1]), "=r"(r[2]), "=r"(r[3]) : "r"(addr));
}
__device__ __forceinline__ void ldsm2(uint32_t* r, uint32_t addr) {
    asm volatile("ldmatrix.sync.aligned.m8n8.x2.shared.b16 {%0,%1}, [%2];"
                 : "=r"(r[0]), "=r"(r[1]) : "r"(addr));
}
__device__ __forceinline__ void ldsm4t(uint32_t* r, uint32_t addr) {
    asm volatile("ldmatrix.sync.aligned.m8n8.x4.trans.shared.b16 {%0,%1,%2,%3}, [%4];"
                 : "=r"(r[0]), "=r"(r[1]), "=r"(r[2]), "=r"(r[3]) : "r"(addr));
}
__device__ __forceinline__ void mma16816h(float* d, const uint32_t* a, const uint32_t* b) {
    asm volatile("mma.sync.aligned.m16n8k16.row.col.f32.f16.f16.f32 "
                 "{%0,%1,%2,%3}, {%4,%5,%6,%7}, {%8,%9}, {%0,%1,%2,%3};"
                 : "+f"(d[0]), "+f"(d[1]), "+f"(d[2]), "+f"(d[3])
                 : "r"(a[0]), "r"(a[1]), "r"(a[2]), "r"(a[3]), "r"(b[0]), "r"(b[1]));
}

// ---------------- fp32 -> fp16 convert (contiguous) ----------------
__global__ void to_fp16(const float* __restrict__ x, __half* __restrict__ y, int n4)
{
    int i = blockIdx.x * blockDim.x + threadIdx.x;
    if (i >= n4) return;
    float4 v = ((const float4*)x)[i];
    ((__half2*)y)[i * 2]     = __floats2half2_rn(v.x, v.y);
    ((__half2*)y)[i * 2 + 1] = __floats2half2_rn(v.z, v.w);
}

// V out of packed QKV (strided read at col NQ_+NKV_) -> fp16
__global__ void conv_v(const float* __restrict__ qkv, __half* __restrict__ v16)
{
    int i = blockIdx.x * blockDim.x + threadIdx.x;   // over MSZ_*128 float4 chunks
    if (i >= MSZ_ * 128) return;
    int row = i >> 7, c4 = (i & 127) * 4;
    float4 v = *(const float4*)(qkv + (size_t)row * NQKV_ + (NQ_ + NKV_) + c4);
    size_t o = ((size_t)row * NKV_ + c4) >> 1;
    ((__half2*)v16)[o]     = __floats2half2_rn(v.x, v.y);
    ((__half2*)v16)[o + 1] = __floats2half2_rn(v.z, v.w);
}

// ---------------- single-pass fp16 HMMA GEMM (4-stage cp.async pipeline) ----------------
#define GSTRIDE 40
#define GTILE_B (128 * GSTRIDE * 2)          // 10240
#define GSTAGE_B (2 * GTILE_B)               // 20480 (A + B)
#define GEMM_SMEM (4 * GSTAGE_B)             // 81920 -> 2 CTA/SM

__global__ void __launch_bounds__(256)
gemm_f16(const __half* __restrict__ A, const __half* __restrict__ Bw,
         float* __restrict__ C, int N, int K)
{
    extern __shared__ char smem[];
    const uint32_t sb = smem_u32(smem);

    const int tid  = threadIdx.x;
    const int lane = tid & 31, warp = tid >> 5;
    const int wm   = warp >> 2;
    const int wn   = warp & 3;
    const size_t by = (size_t)blockIdx.y * 128;
    const size_t bx = (size_t)blockIdx.x * 128;

    const __half* srcA = A  + by * K;
    const __half* srcB = Bw + bx * K;

    const int r0 = tid >> 2,  c0 = (tid & 3);
    const int r1 = r0 + 64;

    auto issue = [&](int kt, int s) {
        const uint32_t base = sb + (uint32_t)s * GSTAGE_B;
        cpasync16(base + (r0 * GSTRIDE + c0 * 8) * 2, srcA + (size_t)r0 * K + kt * 32 + c0 * 8);
        cpasync16(base + (r1 * GSTRIDE + c0 * 8) * 2, srcA + (size_t)r1 * K + kt * 32 + c0 * 8);
        cpasync16(base + GTILE_B + (r0 * GSTRIDE + c0 * 8) * 2, srcB + (size_t)r0 * K + kt * 32 + c0 * 8);
        cpasync16(base + GTILE_B + (r1 * GSTRIDE + c0 * 8) * 2, srcB + (size_t)r1 * K + kt * 32 + c0 * 8);
    };

    float acc[4][4][4];
#pragma unroll
    for (int mt = 0; mt < 4; ++mt)
#pragma unroll
        for (int nt = 0; nt < 4; ++nt)
#pragma unroll
            for (int e = 0; e < 4; ++e) acc[mt][nt][e] = 0.f;

    const int l2 = lane & 15;
    const int arow = wm * 64 + (lane & 15);
    const int acol0 = (lane >> 4) * 8;
    const int brow = wn * 32 + (l2 & 7);
    const int bcol0 = (l2 >> 3) * 8;

    const int KT = K / 32;
    for (int p = 0; p < 3 && p < KT; ++p) { issue(p, p & 3); CP_COMMIT(); }

    for (int kt = 0; kt < KT; ++kt) {
        if (kt + 2 < KT)      CP_WAIT(2);
        else if (kt + 1 < KT) CP_WAIT(1);
        else                  CP_WAIT(0);
        __syncthreads();
        if (kt + 3 < KT) { issue(kt + 3, (kt + 3) & 3); CP_COMMIT(); }

        const uint32_t base = sb + (uint32_t)(kt & 3) * GSTAGE_B;
#pragma unroll
        for (int kk = 0; kk < 32; kk += 16) {
            uint32_t af[4][4], bf[4][2];
#pragma unroll
            for (int mt = 0; mt < 4; ++mt)
                ldsm4(af[mt], base + ((arow + mt * 16) * GSTRIDE + kk + acol0) * 2);
#pragma unroll
            for (int nt = 0; nt < 4; ++nt)
                ldsm2(bf[nt], base + GTILE_B + ((brow + nt * 8) * GSTRIDE + kk + bcol0) * 2);
#pragma unroll
            for (int mt = 0; mt < 4; ++mt)
#pragma unroll
                for (int nt = 0; nt < 4; ++nt)
                    mma16816h(acc[mt][nt], af[mt], bf[nt]);
        }
    }

#pragma unroll
    for (int mt = 0; mt < 4; ++mt) {
        const int row = (int)by + wm * 64 + mt * 16 + (lane >> 2);
#pragma unroll
        for (int nt = 0; nt < 4; ++nt) {
            const int col = (int)bx + wn * 32 + nt * 8 + (lane & 3) * 2;
            *(float2*)(C + (size_t)row * N + col)       = make_float2(acc[mt][nt][0], acc[mt][nt][1]);
            *(float2*)(C + (size_t)(row + 8) * N + col) = make_float2(acc[mt][nt][2], acc[mt][nt][3]);
        }
    }
}

// ---------------- RoPE + RMS-norm -> fp16 (strided source) ----------------
__global__ void rope_rms_f16(const float* __restrict__ buf, int rstride, int coloff, int nh,
                             __half* __restrict__ o16,
                             const float* __restrict__ cosb,
                             const float* __restrict__ sinb)
{
    const int row = blockIdx.x;          // = bs*nh + h
    const int bs  = row / nh;
    const int hh  = row - bs * nh;
    const int s   = bs % S_;
    const float* p = buf + (size_t)bs * rstride + coloff + hh * D_;
    const int t  = threadIdx.x;
    const int dh = t & 63;

    float c  = cosb[s * 64 + dh];
    float sn = sinb[s * 64 + dh];
    float x1 = p[dh];
    float x2 = p[dh + 64];
    float val = (t < 64) ? (x1 * c + x2 * sn) : (x2 * c - x1 * sn);

    float sq = val * val;
#pragma unroll
    for (int o = 16; o; o >>= 1) sq += __shfl_xor_sync(0xffffffffu, sq, o);
    __shared__ float red[4];
    if ((t & 31) == 0) red[t >> 5] = sq;
    __syncthreads();
    float total = red[0] + red[1] + red[2] + red[3];
    float y = val * rsqrtf(total * (1.0f / 128.0f) + 1.1920929e-7f);
    o16[(size_t)row * D_ + t] = __float2half(y);
}

// ---------------- windowed-causal flash attention (single-pass fp16 HMMA) ----------------
// block: 128 queries x 1 head; 8 warps; double-buffered K/V tiles of 64 keys; 2 CTA/SM.
#define LDH 136
#define KV_TILE_B (64 * LDH * 2)     // 17408
#define Q_TILE_B  (128 * LDH * 2)    // 34816
#define ATTN_SMEM (Q_TILE_B + 4 * KV_TILE_B)   // 104448

__global__ void __launch_bounds__(256, 2)
attn_mma(const __half* __restrict__ q16, const __half* __restrict__ k16,
         const __half* __restrict__ v16, __half* __restrict__ ao)
{
    extern __shared__ char smem[];
    const uint32_t sb  = smem_u32(smem);
    const uint32_t Qb  = sb;
    const uint32_t kvb = sb + Q_TILE_B;

    const int mblk = blockIdx.x, h = blockIdx.y, b = blockIdx.z;
    const int q0 = mblk * 128;
    const int hk = h >> 2;
    const int tid = threadIdx.x, lane = tid & 31, w = tid >> 5;

    // Q tile load (once)
    for (int i = tid; i < 2048; i += 256) {
        int r = i >> 4, c = (i & 15) * 8;
        cpasync16(Qb + (uint32_t)(r * LDH + c) * 2,
                  q16 + ((size_t)(b * S_ + q0 + r) * H_ + h) * D_ + c);
    }
    CP_COMMIT();

    float o_acc[16][4];
#pragma unroll
    for (int nt = 0; nt < 16; ++nt)
#pragma unroll
        for (int e = 0; e < 4; ++e) o_acc[nt][e] = 0.f;
    float m_lo = -1e30f, m_hi = -1e30f, l_lo = 0.f, l_hi = 0.f;

    const float scale = 0.08838834764831845f;
    const int t_first = (2 * mblk - 16 > 0) ? (2 * mblk - 16) : 0;
    const int t_last  = 2 * mblk + 1;
    const int lane2 = lane & 15;

    auto issue_kv = [&](int t, int s) {
        const uint32_t base = kvb + (uint32_t)s * 2 * KV_TILE_B;
        for (int i = tid; i < 1024; i += 256) {
            int r = i >> 4, c = (i & 15) * 8;
            size_t g = ((size_t)(b * S_ + t * 64 + r) * KV_ + hk) * D_ + c;
            uint32_t o = (uint32_t)(r * LDH + c) * 2;
            cpasync16(base + o, k16 + g);
            cpasync16(base + KV_TILE_B + o, v16 + g);
        }
    };
    issue_kv(t_first, t_first & 1);
    CP_COMMIT();

    const uint32_t a_off = (uint32_t)((w * 16 + (lane & 15)) * LDH + (lane >> 4) * 8) * 2;
    const int i_lo = q0 + w * 16 + (lane >> 2);
    const int i_hi = i_lo + 8;

    for (int t = t_first; t <= t_last; ++t) {
        const int j0 = t * 64;
        __syncthreads();                       // stage being overwritten is free
        if (t < t_last) { issue_kv(t + 1, (t + 1) & 1); CP_COMMIT(); CP_WAIT(1); }
        else            { CP_WAIT(0); }
        __syncthreads();

        const uint32_t Kb = kvb + (uint32_t)(t & 1) * 2 * KV_TILE_B;
        const uint32_t Vb = Kb + KV_TILE_B;

        // ---- S = Q K^T (fp16 single-pass) ----
        float s[8][4];
#pragma unroll
        for (int nt = 0; nt < 8; ++nt)
#pragma unroll
            for (int e = 0; e < 4; ++e) s[nt][e] = 0.f;

#pragma unroll
        for (int kk = 0; kk < 128; kk += 16) {
            uint32_t aq[4];
            ldsm4(aq, Qb + a_off + kk * 2);
#pragma unroll
            for (int nt = 0; nt < 8; ++nt) {
                uint32_t bk[2];
                ldsm2(bk, Kb + (uint32_t)((nt * 8 + (lane2 & 7)) * LDH + kk + ((lane2 >> 3) & 1) * 8) * 2);
                mma16816h(s[nt], aq, bk);
            }
        }

        // ---- masked online softmax ----
        float mx_lo = -1e30f, mx_hi = -1e30f;
#pragma unroll
        for (int nt = 0; nt < 8; ++nt) {
            int jb = j0 + nt * 8 + (lane & 3) * 2;
            bool v0 = (jb     <= i_lo) && (i_lo - jb     < WIN_);
            bool v1 = (jb + 1 <= i_lo) && (i_lo - jb - 1 < WIN_);
            bool v2 = (jb     <= i_hi) && (i_hi - jb     < WIN_);
            bool v3 = (jb + 1 <= i_hi) && (i_hi - jb - 1 < WIN_);
            s[nt][0] = v0 ? s[nt][0] * scale : -1e30f;
            s[nt][1] = v1 ? s[nt][1] * scale : -1e30f;
            s[nt][2] = v2 ? s[nt][2] * scale : -1e30f;
            s[nt][3] = v3 ? s[nt][3] * scale : -1e30f;
            mx_lo = fmaxf(mx_lo, fmaxf(s[nt][0], s[nt][1]));
            mx_hi = fmaxf(mx_hi, fmaxf(s[nt][2], s[nt][3]));
        }
        mx_lo = fmaxf(mx_lo, __shfl_xor_sync(0xffffffffu, mx_lo, 1));
        mx_lo = fmaxf(mx_lo, __shfl_xor_sync(0xffffffffu, mx_lo, 2));
        mx_hi = fmaxf(mx_hi, __shfl_xor_sync(0xffffffffu, mx_hi, 1));
        mx_hi = fmaxf(mx_hi, __shfl_xor_sync(0xffffffffu, mx_hi, 2));

        float mn_lo = fmaxf(m_lo, mx_lo), mn_hi = fmaxf(m_hi, mx_hi);
        float al_lo = __expf(m_lo - mn_lo), al_hi = __expf(m_hi - mn_hi);
        float sum_lo = 0.f, sum_hi = 0.f;
#pragma unroll
        for (int nt = 0; nt < 8; ++nt) {
            s[nt][0] = __expf(s[nt][0] - mn_lo);
            s[nt][1] = __expf(s[nt][1] - mn_lo);
            s[nt][2] = __expf(s[nt][2] - mn_hi);
            s[nt][3] = __expf(s[nt][3] - mn_hi);
            sum_lo += s[nt][0] + s[nt][1];
            sum_hi += s[nt][2] + s[nt][3];
        }
        sum_lo += __shfl_xor_sync(0xffffffffu, sum_lo, 1);
        sum_lo += __shfl_xor_sync(0xffffffffu, sum_lo, 2);
        sum_hi += __shfl_xor_sync(0xffffffffu, sum_hi, 1);
        sum_hi += __shfl_xor_sync(0xffffffffu, sum_hi, 2);
        l_lo = l_lo * al_lo + sum_lo;  m_lo = mn_lo;
        l_hi = l_hi * al_hi + sum_hi;  m_hi = mn_hi;
#pragma unroll
        for (int nt = 0; nt < 16; ++nt) {
            o_acc[nt][0] *= al_lo; o_acc[nt][1] *= al_lo;
            o_acc[nt][2] *= al_hi; o_acc[nt][3] *= al_hi;
        }

        // ---- O += P V (fp16 single-pass) ----
#pragma unroll
        for (int kc = 0; kc < 4; ++kc) {
            uint32_t ap[4];
            __half2 p0 = __floats2half2_rn(s[2*kc][0],   s[2*kc][1]);
            __half2 p1 = __floats2half2_rn(s[2*kc][2],   s[2*kc][3]);
            __half2 p2 = __floats2half2_rn(s[2*kc+1][0], s[2*kc+1][1]);
            __half2 p3 = __floats2half2_rn(s[2*kc+1][2], s[2*kc+1][3]);
            ap[0] = *(uint32_t*)&p0; ap[1] = *(uint32_t*)&p1;
            ap[2] = *(uint32_t*)&p2; ap[3] = *(uint32_t*)&p3;

            uint32_t vr = (uint32_t)(kc * 16 + (lane & 7) + ((lane >> 3) & 1) * 8) * LDH
                        + (uint32_t)((lane >> 4) * 8);
#pragma unroll
            for (int dt = 0; dt < 8; ++dt) {
                uint32_t bv[4];
                ldsm4t(bv, Vb + (vr + dt * 16) * 2);
                mma16816h(o_acc[2*dt],   ap, bv);
                mma16816h(o_acc[2*dt+1], ap, bv + 2);
            }
        }
    }

    // ---- epilogue: normalize, write fp16 ----
    float inv_lo = 1.0f / l_lo, inv_hi = 1.0f / l_hi;
#pragma unroll
    for (int nt = 0; nt < 16; ++nt) {
        int c = nt * 8 + (lane & 3) * 2;
        size_t glo = ((size_t)(b * S_ + i_lo) * H_ + h) * D_ + c;
        size_t ghi = ((size_t)(b * S_ + i_hi) * H_ + h) * D_ + c;
        *(__half2*)(ao + glo) = __floats2half2_rn(o_acc[nt][0] * inv_lo, o_acc[nt][1] * inv_lo);
        *(__half2*)(ao + ghi) = __floats2half2_rn(o_acc[nt][2] * inv_hi, o_acc[nt][3] * inv_hi);
    }
}

// ---------------- launch ----------------
extern "C" void kernel_launch(void* const* d_in, const int* in_sizes, int n_in,
                              void* d_out, int out_size)
{
    (void)in_sizes; (void)n_in; (void)out_size;
    const float* x    = (const float*)d_in[0];
    const float* cosb = (const float*)d_in[1];
    const float* sinb = (const float*)d_in[2];
    const float* Wq   = (const float*)d_in[3];
    const float* Wk   = (const float*)d_in[4];
    const float* Wv   = (const float*)d_in[5];
    const float* Wo   = (const float*)d_in[6];
    float* out = (float*)d_out;

    float* qkv;
    cudaGetSymbolAddress((void**)&qkv, g_qkv);
    __half *x16, *wp16, *wo16, *ao16, *q16, *k16, *v16;
    cudaGetSymbolAddress((void**)&x16,  g_x16);
    cudaGetSymbolAddress((void**)&wp16, g_wp16);
    cudaGetSymbolAddress((void**)&wo16, g_wo16);
    cudaGetSymbolAddress((void**)&ao16, g_ao16);
    cudaGetSymbolAddress((void**)&q16,  g_q16);
    cudaGetSymbolAddress((void**)&k16,  g_k16);
    cudaGetSymbolAddress((void**)&v16,  g_v16);

    const int M = MSZ_;   // 4096
    cudaFuncSetAttribute(gemm_f16, cudaFuncAttributeMaxDynamicSharedMemorySize, GEMM_SMEM);
    cudaFuncSetAttribute(attn_mma, cudaFuncAttributeMaxDynamicSharedMemorySize, ATTN_SMEM);

    auto CVT = [](const float* src, __half* dst, size_t n) {
        int n4 = (int)(n / 4);
        to_fp16<<<(n4 + 255) / 256, 256>>>(src, dst, n4);
    };

    // fp16 conversions: x, packed W(q|k|v), Wo
    CVT(x,  x16, (size_t)M * E_);
    CVT(Wq, wp16,                          (size_t)NQ_ * E_);
    CVT(Wk, wp16 + (size_t)NQ_ * E_,       (size_t)NKV_ * E_);
    CVT(Wv, wp16 + (size_t)(NQ_+NKV_)*E_,  (size_t)NKV_ * E_);
    CVT(Wo, wo16, (size_t)E_ * NQ_);

    // fused QKV projection (fp16 single-pass)
    gemm_f16<<<dim3(NQKV_ / 128, M / 128), 256, GEMM_SMEM>>>(x16, wp16, qkv, NQKV_, E_);

    // v convert + rope/rms for q, k (fp16)
    conv_v<<<(M * 128 + 255) / 256, 256>>>(qkv, v16);
    rope_rms_f16<<<M * H_,  128>>>(qkv, NQKV_, 0,   H_,  q16, cosb, sinb);
    rope_rms_f16<<<M * KV_, 128>>>(qkv, NQKV_, NQ_, KV_, k16, cosb, sinb);

    // attention (fp16 single-pass, 2 CTA/SM)
    attn_mma<<<dim3(S_ / 128, H_, B_), 256, ATTN_SMEM>>>(q16, k16, v16, ao16);

    // output projection (fp16 single-pass)
    gemm_f16<<<dim3(E_ / 128, M / 128), 256, GEMM_SMEM>>>(ao16, wo16, out, E_, NQ_);
}